// round 12
// baseline (speedup 1.0000x reference)
#include <cuda_runtime.h>
#include <cuda_fp16.h>
#include <cstdint>
#include <cstddef>

// Problem constants
#define B_ 4
#define T_ 2048
#define KD_ 128
#define H_ 8
#define C_ 1024   // KD_*H_
#define PSPLIT 4

// Scratch (device globals; no allocation allowed)
__device__ __align__(256) __half g_Wq5[(size_t)5 * C_ * KD_];     // [tap][f(perm)][cin]
__device__ __align__(256) __half g_Wk5[(size_t)5 * C_ * KD_];
__device__ __align__(256) __half g_Wv [(size_t)C_ * KD_];         // [f(perm)][cin]
__device__ __align__(256) __half g_Wu [(size_t)KD_ * C_];         // [cout][f]
__device__ __align__(256) __half g_Qh [(size_t)32 * T_ * KD_];    // [b][t][f] == [m][t'][d]
__device__ __align__(256) __half g_Kh [(size_t)32 * T_ * KD_];
__device__ __align__(256) __half g_Vh [(size_t)32 * T_ * KD_];
__device__ __align__(256) __half g_Ph [(size_t)B_ * T_ * C_];     // attn out [b][t][f]
__device__ __align__(256) float  g_acc[(size_t)PSPLIT * B_ * T_ * KD_];  // proj partials

__device__ __forceinline__ uint32_t smem_to_u32(const void* p) {
    uint32_t a;
    asm("{ .reg .u64 t; cvta.to.shared.u64 t, %1; cvt.u32.u64 %0, t; }" : "=r"(a) : "l"(p));
    return a;
}

#define LDMATRIX_X4(r0, r1, r2, r3, addr) \
    asm volatile("ldmatrix.sync.aligned.m8n8.x4.shared.b16 {%0,%1,%2,%3}, [%4];" \
        : "=r"(r0), "=r"(r1), "=r"(r2), "=r"(r3) : "r"(addr))
#define LDMATRIX_X4_T(r0, r1, r2, r3, addr) \
    asm volatile("ldmatrix.sync.aligned.m8n8.x4.trans.shared.b16 {%0,%1,%2,%3}, [%4];" \
        : "=r"(r0), "=r"(r1), "=r"(r2), "=r"(r3) : "r"(addr))
#define MMA_16816(c, a, b0v, b1v) \
    asm volatile("mma.sync.aligned.m16n8k16.row.col.f32.f16.f16.f32 " \
        "{%0,%1,%2,%3},{%4,%5,%6,%7},{%8,%9},{%0,%1,%2,%3};" \
        : "+f"((c)[0]), "+f"((c)[1]), "+f"((c)[2]), "+f"((c)[3]) \
        : "r"((a)[0]), "r"((a)[1]), "r"((a)[2]), "r"((a)[3]), "r"(b0v), "r"(b1v))

#define CP_ASYNC16(dst, src) \
    asm volatile("cp.async.cg.shared.global [%0], [%1], 16;" :: "r"(dst), "l"(src))
#define CP_COMMIT() asm volatile("cp.async.commit_group;" ::: "memory")
template<int N> __device__ __forceinline__ void cp_wait() {
    asm volatile("cp.async.wait_group %0;" :: "n"(N) : "memory");
}

__device__ __forceinline__ float silu_f(float y) { return y / (1.0f + __expf(-y)); }

// ===========================================================================
// Weight prepack (x is now converted inside qkvconv). Wq/Wk/Wv cout rows are
// PERMUTED: row f holds original channel c = ((f&127)<<3)|(f>>7).
// ===========================================================================
#define N_W5 (5 * C_ * KD_)         // 655360
#define N_WV (C_ * KD_)             // 131072
#define N_WU (KD_ * C_)             // 131072
#define N_PACK (2 * N_W5 + N_WV + N_WU)

__global__ void pack_all_kernel(
    const float* __restrict__ Wq, const float* __restrict__ Wk,
    const float* __restrict__ Wv, const float* __restrict__ Wu,
    __half* __restrict__ wq5, __half* __restrict__ wk5,
    __half* __restrict__ wv, __half* __restrict__ wu)
{
    int i = blockIdx.x * 256 + threadIdx.x;
    if (i < N_W5) {
        int cin = i & 127, f = (i >> 7) & 1023, j = i >> 17;
        int c = ((f & 127) << 3) | (f >> 7);
        wq5[i] = __float2half(Wq[((c << 7) + cin) * 5 + j]);
        return;
    }
    i -= N_W5;
    if (i < N_W5) {
        int cin = i & 127, f = (i >> 7) & 1023, j = i >> 17;
        int c = ((f & 127) << 3) | (f >> 7);
        wk5[i] = __float2half(Wk[((c << 7) + cin) * 5 + j]);
        return;
    }
    i -= N_W5;
    if (i < N_WV) {
        int cin = i & 127, f = i >> 7;
        int c = ((f & 127) << 3) | (f >> 7);
        wv[i] = __float2half(Wv[(c << 7) + cin]);
        return;
    }
    i -= N_WV;
    if (i < N_WU) { wu[i] = __float2half(Wu[i]); }
}

// ===========================================================================
// Merged Q/K/V conv kernel. 128 threads / 4 warps, M=32 rows per warp.
// A loaded DIRECTLY from fp32 x (converted during smem fill; A loaded once).
// B double-buffered cp.async over taps; permuted weights -> coalesced stores.
// blockIdx.y: 0-7 Q tiles, 8-15 K tiles, 16-23 V tiles (1 tap, row off 8).
// ===========================================================================
#define QKV_SMEM (34816 + 2 * 32768)

__global__ void __launch_bounds__(128, 2) qkvconv_kernel(
    const float* __restrict__ X,
    const __half* __restrict__ Wq5, const __half* __restrict__ Wk5,
    const __half* __restrict__ Wv,
    const float* __restrict__ bq, const float* __restrict__ bk,
    __half* __restrict__ Qo, __half* __restrict__ Ko, __half* __restrict__ Vo,
    float qk_scale)
{
    extern __shared__ char smc[];
    const uint32_t sA  = smem_to_u32(smc);
    const uint32_t sB0 = sA + 34816;

    const int t0 = blockIdx.x * 128;
    const int cm = blockIdx.y;
    const int mat = cm >> 3;                 // 0=Q 1=K 2=V
    const int c0 = (cm & 7) * 128;           // f-tile base
    const int b  = blockIdx.z;
    const __half* Bw  = (mat == 0) ? Wq5 : (mat == 1) ? Wk5 : Wv;
    const float* bias = (mat == 0) ? bq  : (mat == 1) ? bk  : nullptr;
    __half* out       = (mat == 0) ? Qo  : (mat == 1) ? Ko  : Vo;
    const float scale = (mat == 2) ? 1.0f : qk_scale;
    const int ntaps   = (mat == 2) ? 1 : 5;

    const int tid = threadIdx.x, w = tid >> 5, l = tid & 31;
    const int mi = l >> 3;

    // ---- prefetch B tap 0 into buf 0 (32KB / 128 thr = 16 x 16B each)
    #pragma unroll
    for (int it = 0; it < 16; it++) {
        int idx = it * 128 + tid;
        int r = idx >> 4, cb = idx & 15;
        CP_ASYNC16(sB0 + r * 256 + ((cb ^ (r & 7)) << 4),
                   Bw + ((size_t)(c0 + r)) * 128 + cb * 8);
    }
    CP_COMMIT();

    // ---- load A rows t0-8 .. t0+127 (136 rows) from fp32 x, convert to fp16
    #pragma unroll
    for (int it = 0; it < 17; it++) {
        int idx = it * 128 + tid;
        if (idx < 136 * 16) {
            int r = idx >> 4, cb = idx & 15;
            int tg = t0 + r - 8;
            uint4 v = make_uint4(0u, 0u, 0u, 0u);
            if (tg >= 0 && tg < T_) {
                const float4* src = (const float4*)(X + ((size_t)b * T_ + tg) * 128);
                float4 f0 = src[cb * 2], f1 = src[cb * 2 + 1];
                __half2 h0 = __floats2half2_rn(f0.x, f0.y);
                __half2 h1 = __floats2half2_rn(f0.z, f0.w);
                __half2 h2 = __floats2half2_rn(f1.x, f1.y);
                __half2 h3 = __floats2half2_rn(f1.z, f1.w);
                v = make_uint4(*(uint32_t*)&h0, *(uint32_t*)&h1,
                               *(uint32_t*)&h2, *(uint32_t*)&h3);
            }
            *(uint4*)(smc + r * 256 + ((cb ^ (r & 7)) << 4)) = v;
        }
    }

    float cacc[2][16][4] = {};

    #pragma unroll 1
    for (int j = 0; j < ntaps; j++) {
        __syncthreads();   // prior compute done (protects buf (j+1)&1); A stores for j=0
        if (j + 1 < ntaps) {
            const uint32_t sBn = sB0 + ((j + 1) & 1) * 32768;
            #pragma unroll
            for (int it = 0; it < 16; it++) {
                int idx = it * 128 + tid;
                int r = idx >> 4, cb = idx & 15;
                CP_ASYNC16(sBn + r * 256 + ((cb ^ (r & 7)) << 4),
                           Bw + ((size_t)(j + 1) * C_ + c0 + r) * 128 + cb * 8);
            }
            CP_COMMIT();
            cp_wait<1>();
        } else {
            cp_wait<0>();
        }
        __syncthreads();

        const uint32_t sB = sB0 + (j & 1) * 32768;
        const int rowoff = (mat == 2) ? 8 : 2 * j;  // A row = out row + rowoff
        #pragma unroll
        for (int kc = 0; kc < 8; kc++) {
            uint32_t a4[2][4];
            #pragma unroll
            for (int rg = 0; rg < 2; rg++) {
                const int rr = w * 32 + rg * 16 + (mi & 1) * 8 + (l & 7) + rowoff;
                const int cba = kc * 2 + (mi >> 1);
                LDMATRIX_X4(a4[rg][0], a4[rg][1], a4[rg][2], a4[rg][3],
                            sA + rr * 256 + ((cba ^ (rr & 7)) << 4));
            }
            #pragma unroll
            for (int jn = 0; jn < 16; jn += 2) {
                const int nr = (jn + (mi >> 1)) * 8 + (l & 7);
                const int cbb = kc * 2 + (mi & 1);
                uint32_t b0, b1, b2, b3;
                LDMATRIX_X4(b0, b1, b2, b3, sB + nr * 256 + ((cbb ^ (nr & 7)) << 4));
                MMA_16816(cacc[0][jn],     a4[0], b0, b1);
                MMA_16816(cacc[0][jn + 1], a4[0], b2, b3);
                MMA_16816(cacc[1][jn],     a4[1], b0, b1);
                MMA_16816(cacc[1][jn + 1], a4[1], b2, b3);
            }
        }
    }

    // ---- epilogue: bias(perm) + silu + scale, COALESCED half2 stores [b][t][f]
    #pragma unroll
    for (int rg = 0; rg < 2; rg++) {
        const int tr0 = t0 + w * 32 + rg * 16 + (l >> 2);
        const int tr1 = tr0 + 8;
        #pragma unroll
        for (int jn = 0; jn < 16; jn++) {
            const int f = c0 + 8 * jn + 2 * (l & 3);
            float bv0 = 0.0f, bv1 = 0.0f;
            if (mat < 2) {
                const int co = ((f & 127) << 3) | (f >> 7);   // original channel
                bv0 = bias[co];
                bv1 = bias[co + 8];                            // f+1 -> k+1 -> c+8
            }
            float s00 = silu_f(cacc[rg][jn][0] + bv0) * scale;
            float s01 = silu_f(cacc[rg][jn][1] + bv1) * scale;
            float s10 = silu_f(cacc[rg][jn][2] + bv0) * scale;
            float s11 = silu_f(cacc[rg][jn][3] + bv1) * scale;
            *(__half2*)(out + ((size_t)b * T_ + tr0) * C_ + f) = __floats2half2_rn(s00, s01);
            *(__half2*)(out + ((size_t)b * T_ + tr1) * C_ + f) = __floats2half2_rn(s10, s11);
        }
    }
}

// ===========================================================================
// Projection with split-K: partial GEMM (no act) + reduce(bias+silu).
// Both K-chunks prefetched via cp.async at CTA start (2 groups, 128KB smem).
// ===========================================================================
#define PROJ_SMEM 131072

__global__ void __launch_bounds__(256, 1) proj_partial_kernel(
    const __half* __restrict__ A, const __half* __restrict__ Bw,
    float* __restrict__ part)
{
    extern __shared__ char smc[];
    const uint32_t sBase = smem_to_u32(smc);

    const int t0 = blockIdx.x * 128;
    const int sp = blockIdx.y;
    const int b  = blockIdx.z;
    const int tid = threadIdx.x, w = tid >> 5, l = tid & 31;
    const int mi = l >> 3;

    #pragma unroll
    for (int ch = 0; ch < 2; ch++) {
        const int cin0 = sp * 256 + ch * 128;
        const uint32_t sA = sBase + ch * 65536;
        const uint32_t sB = sA + 32768;
        #pragma unroll
        for (int it = 0; it < 8; it++) {
            int idx = it * 256 + tid;
            int r = idx >> 4, cb = idx & 15;
            int off = r * 256 + ((cb ^ (r & 7)) << 4);
            CP_ASYNC16(sA + off, A + ((size_t)b * T_ + t0 + r) * C_ + cin0 + cb * 8);
            CP_ASYNC16(sB + off, Bw + (size_t)r * C_ + cin0 + cb * 8);
        }
        CP_COMMIT();
    }

    float cacc[16][4] = {};

    #pragma unroll
    for (int ch = 0; ch < 2; ch++) {
        if (ch == 0) cp_wait<1>(); else cp_wait<0>();
        __syncthreads();
        const uint32_t sA = sBase + ch * 65536;
        const uint32_t sB = sA + 32768;
        #pragma unroll
        for (int kc = 0; kc < 8; kc++) {
            uint32_t a4[4];
            const int rr = w * 16 + (mi & 1) * 8 + (l & 7);
            const int cba = kc * 2 + (mi >> 1);
            LDMATRIX_X4(a4[0], a4[1], a4[2], a4[3],
                        sA + rr * 256 + ((cba ^ (rr & 7)) << 4));
            #pragma unroll
            for (int jn = 0; jn < 16; jn += 2) {
                const int nr = (jn + (mi >> 1)) * 8 + (l & 7);
                const int cbb = kc * 2 + (mi & 1);
                uint32_t b0, b1, b2, b3;
                LDMATRIX_X4(b0, b1, b2, b3, sB + nr * 256 + ((cbb ^ (nr & 7)) << 4));
                MMA_16816(cacc[jn],     a4, b0, b1);
                MMA_16816(cacc[jn + 1], a4, b2, b3);
            }
        }
    }

    const int tr0 = t0 + w * 16 + (l >> 2);
    const int tr1 = tr0 + 8;
    float* dst = part + (size_t)sp * (B_ * T_ * KD_);
    #pragma unroll
    for (int jn = 0; jn < 16; jn++) {
        const int c = 8 * jn + 2 * (l & 3);
        *(float2*)(dst + ((size_t)b * T_ + tr0) * KD_ + c) = make_float2(cacc[jn][0], cacc[jn][1]);
        *(float2*)(dst + ((size_t)b * T_ + tr1) * KD_ + c) = make_float2(cacc[jn][2], cacc[jn][3]);
    }
}

__global__ void proj_reduce_kernel(const float* __restrict__ part,
                                   const float* __restrict__ bu,
                                   float* __restrict__ out)
{
    const int i = blockIdx.x * 256 + threadIdx.x;   // over B*T*128
    const int c = i & 127;
    const int S = B_ * T_ * KD_;
    float s = part[i] + part[i + S] + part[i + 2 * S] + part[i + 3 * S];
    out[i] = silu_f(s + bu[c]);
}

// ===========================================================================
// Flash attention via mma.sync. BM=256 (8 warps x M=32 rows): K/V B-frags
// shared across two row-groups -> LDS per MMA 256B -> 160B. Q frags
// reloaded from smem per k-chunk (register budget). K/V loaded in pairs of
// 64-row s-tiles, double-buffered cp.async.
// Smem: Q 64KB | buf0 [K32|V32] | buf1 [K32|V32] = 192KB.
// ===========================================================================
#define BM 256
#define BN 64
#define ATTN_SMEM (65536 + 2 * 65536)

__global__ void __launch_bounds__(256, 1)
attn_mma_kernel(const __half* __restrict__ Qb, const __half* __restrict__ Kb,
                const __half* __restrict__ Vb, __half* __restrict__ Ph)
{
    extern __shared__ char smc[];
    const uint32_t sQ = smem_to_u32(smc);

    const int tid = threadIdx.x, w = tid >> 5, l = tid & 31;
    const int bid = blockIdx.x;
    const int bi  = 7 - (bid >> 5);        // q-tile index, heavy (7) first
    const int m   = bid & 31;
    const int q0  = bi * BM;
    const size_t mbase = (size_t)m * T_ * KD_;
    const int npairs = 2 * bi + 2;         // pairs of 64-row s-tiles (128 rows each)
    const int mi = l >> 3;

    // ---- prefetch pair 0 (128 K rows + 128 V rows) into buf 0
    {
        const __half* ks = Kb + mbase;
        const __half* vs = Vb + mbase;
        #pragma unroll
        for (int it = 0; it < 8; it++) {
            int idx = it * 256 + tid;
            int r = idx >> 4, cb = idx & 15;
            int off = r * 256 + ((cb ^ (r & 7)) << 4);
            CP_ASYNC16(sQ + 65536 + off,         ks + (size_t)r * KD_ + cb * 8);
            CP_ASYNC16(sQ + 65536 + 32768 + off, vs + (size_t)r * KD_ + cb * 8);
        }
        CP_COMMIT();
    }

    // ---- load Q tile [256 x 128] into swizzled smem (64KB)
    {
        const uint4* src = (const uint4*)(Qb + mbase + (size_t)q0 * KD_);
        #pragma unroll
        for (int it = 0; it < 16; it++) {
            int idx = it * 256 + tid;
            int r = idx >> 4, cb = idx & 15;
            uint4 v = src[idx];
            *(uint4*)(smc + r * 256 + ((cb ^ (r & 7)) << 4)) = v;
        }
    }
    __syncthreads();

    float oacc[2][16][4] = {};
    float ls0[2] = {0.0f, 0.0f}, ls1[2] = {0.0f, 0.0f};
    // per-rg global row bases
    const int rbase0 = q0 + w * 32 + (l >> 2);        // rg=0 row0
    // rg row0 = rbase0 + rg*16 ; row1 = +8

    #pragma unroll 1
    for (int p = 0; p < npairs; p++) {
        __syncthreads();   // prior compute done (protects buf (p+1)&1)
        if (p + 1 < npairs) {
            const int s1 = (p + 1) * 128;
            const uint32_t base = sQ + 65536 + ((p + 1) & 1) * 65536;
            const __half* ks = Kb + mbase + (size_t)s1 * KD_;
            const __half* vs = Vb + mbase + (size_t)s1 * KD_;
            #pragma unroll
            for (int it = 0; it < 8; it++) {
                int idx = it * 256 + tid;
                int r = idx >> 4, cb = idx & 15;
                int off = r * 256 + ((cb ^ (r & 7)) << 4);
                CP_ASYNC16(base + off,         ks + (size_t)r * KD_ + cb * 8);
                CP_ASYNC16(base + 32768 + off, vs + (size_t)r * KD_ + cb * 8);
            }
            CP_COMMIT();
            cp_wait<1>();
        } else {
            cp_wait<0>();
        }
        __syncthreads();

        const uint32_t bufK = sQ + 65536 + (p & 1) * 65536;
        const uint32_t bufV = bufK + 32768;

        #pragma unroll
        for (int sub = 0; sub < 2; sub++) {
            const int s0 = p * 128 + sub * BN;
            const uint32_t sK = bufK + sub * 16384;
            const uint32_t sV = bufV + sub * 16384;

            // ---- S = Q K^T  (log2-domain), B-frags shared across 2 row-groups
            float sacc[2][8][4] = {};
            #pragma unroll
            for (int kc = 0; kc < 8; kc++) {
                uint32_t kb[4][4];
                #pragma unroll
                for (int jj = 0; jj < 4; jj++) {
                    const int nr = (jj * 2 + (mi >> 1)) * 8 + (l & 7);
                    const int cb = kc * 2 + (mi & 1);
                    LDMATRIX_X4(kb[jj][0], kb[jj][1], kb[jj][2], kb[jj][3],
                                sK + nr * 256 + ((cb ^ (nr & 7)) << 4));
                }
                #pragma unroll
                for (int rg = 0; rg < 2; rg++) {
                    uint32_t qa4[4];
                    const int rr = w * 32 + rg * 16 + (mi & 1) * 8 + (l & 7);
                    const int cba = kc * 2 + (mi >> 1);
                    LDMATRIX_X4(qa4[0], qa4[1], qa4[2], qa4[3],
                                sQ + rr * 256 + ((cba ^ (rr & 7)) << 4));
                    #pragma unroll
                    for (int jj = 0; jj < 4; jj++) {
                        MMA_16816(sacc[rg][2 * jj],     qa4, kb[jj][0], kb[jj][1]);
                        MMA_16816(sacc[rg][2 * jj + 1], qa4, kb[jj][2], kb[jj][3]);
                    }
                }
            }

            // ---- mask + ex2.f16x2 -> P A-frags
            uint32_t pa[2][4][4];
            #pragma unroll
            for (int rg = 0; rg < 2; rg++) {
                const int r0g = rbase0 + rg * 16;
                const int r1g = r0g + 8;
                const int cb0 = s0 + 2 * (l & 3);
                float lad0 = 0.0f, lad1 = 0.0f;
                #pragma unroll
                for (int j = 0; j < 8; j++) {
                    const int c0 = cb0 + 8 * j, c1 = c0 + 1;
                    float m00 = (c0 <= r0g) ? sacc[rg][j][0] : -60.0f;
                    float m01 = (c1 <= r0g) ? sacc[rg][j][1] : -60.0f;
                    float m10 = (c0 <= r1g) ? sacc[rg][j][2] : -60.0f;
                    float m11 = (c1 <= r1g) ? sacc[rg][j][3] : -60.0f;
                    __half2 ha = __floats2half2_rn(m00, m01);
                    __half2 hb = __floats2half2_rn(m10, m11);
                    uint32_t ua, ub;
                    asm("ex2.approx.f16x2 %0, %1;" : "=r"(ua) : "r"(*(uint32_t*)&ha));
                    asm("ex2.approx.f16x2 %0, %1;" : "=r"(ub) : "r"(*(uint32_t*)&hb));
                    float2 fa = __half22float2(*(__half2*)&ua);
                    float2 fb = __half22float2(*(__half2*)&ub);
                    lad0 += fa.x + fa.y;
                    lad1 += fb.x + fb.y;
                    const int kc2 = j >> 1, hi = (j & 1) * 2;
                    pa[rg][kc2][hi + 0] = ua;
                    pa[rg][kc2][hi + 1] = ub;
                }
                ls0[rg] += lad0;
                ls1[rg] += lad1;
            }

            // ---- O += P V   (V B-frags shared across 2 row-groups)
            #pragma unroll
            for (int kc2 = 0; kc2 < 4; kc2++) {
                #pragma unroll
                for (int ji = 0; ji < 8; ji++) {
                    const int sr = kc2 * 16 + (mi & 1) * 8 + (l & 7);
                    const int cb = 2 * ji + (mi >> 1);
                    uint32_t b0, b1, b2, b3;
                    LDMATRIX_X4_T(b0, b1, b2, b3, sV + sr * 256 + ((cb ^ (sr & 7)) << 4));
                    MMA_16816(oacc[0][2 * ji],     pa[0][kc2], b0, b1);
                    MMA_16816(oacc[0][2 * ji + 1], pa[0][kc2], b2, b3);
                    MMA_16816(oacc[1][2 * ji],     pa[1][kc2], b0, b1);
                    MMA_16816(oacc[1][2 * ji + 1], pa[1][kc2], b2, b3);
                }
            }
        }
    }

    // ---- epilogue
    const int b = m >> 3, h = m & 7;
    #pragma unroll
    for (int rg = 0; rg < 2; rg++) {
        float l0 = ls0[rg], l1 = ls1[rg];
        l0 += __shfl_xor_sync(0xffffffffu, l0, 1);
        l0 += __shfl_xor_sync(0xffffffffu, l0, 2);
        l1 += __shfl_xor_sync(0xffffffffu, l1, 1);
        l1 += __shfl_xor_sync(0xffffffffu, l1, 2);
        const float li0 = 1.0f / l0, li1 = 1.0f / l1;
        const int r0g = rbase0 + rg * 16;
        const int r1g = r0g + 8;
        __half* base0 = Ph + ((size_t)b * T_ + r0g) * C_ + h * KD_ + 2 * (l & 3);
        __half* base1 = Ph + ((size_t)b * T_ + r1g) * C_ + h * KD_ + 2 * (l & 3);
        #pragma unroll
        for (int j = 0; j < 16; j++) {
            *(__half2*)(base0 + 8 * j) = __floats2half2_rn(oacc[rg][j][0] * li0, oacc[rg][j][1] * li0);
            *(__half2*)(base1 + 8 * j) = __floats2half2_rn(oacc[rg][j][2] * li1, oacc[rg][j][3] * li1);
        }
    }
}

// ===========================================================================
extern "C" void kernel_launch(void* const* d_in, const int* in_sizes, int n_in,
                              void* d_out, int out_size)
{
    const float* x  = (const float*)d_in[0];
    const float* Wq = (const float*)d_in[1];
    const float* bq = (const float*)d_in[2];
    const float* Wk = (const float*)d_in[3];
    const float* bk = (const float*)d_in[4];
    const float* Wv = (const float*)d_in[5];
    const float* Wu = (const float*)d_in[6];
    const float* bu = (const float*)d_in[7];
    float* out = (float*)d_out;

    __half *wq5, *wk5, *wv, *wu, *qp, *kp, *vp, *ph;
    float* pacc;
    cudaGetSymbolAddress((void**)&wq5,  g_Wq5);
    cudaGetSymbolAddress((void**)&wk5,  g_Wk5);
    cudaGetSymbolAddress((void**)&wv,   g_Wv);
    cudaGetSymbolAddress((void**)&wu,   g_Wu);
    cudaGetSymbolAddress((void**)&qp,   g_Qh);
    cudaGetSymbolAddress((void**)&kp,   g_Kh);
    cudaGetSymbolAddress((void**)&vp,   g_Vh);
    cudaGetSymbolAddress((void**)&ph,   g_Ph);
    cudaGetSymbolAddress((void**)&pacc, g_acc);

    cudaFuncSetAttribute(attn_mma_kernel, cudaFuncAttributeMaxDynamicSharedMemorySize, ATTN_SMEM);
    cudaFuncSetAttribute(qkvconv_kernel, cudaFuncAttributeMaxDynamicSharedMemorySize, QKV_SMEM);
    cudaFuncSetAttribute(proj_partial_kernel, cudaFuncAttributeMaxDynamicSharedMemorySize, PROJ_SMEM);

    // 1/128^0.25 * sqrt(log2(e))  -> S lands in log2 domain
    const float qk_scale = 0.3570958376f;

    // ---- weight prepack (x converted inside qkvconv)
    pack_all_kernel<<<N_PACK / 256, 256>>>(Wq, Wk, Wv, Wu, wq5, wk5, wv, wu);

    // ---- merged Q/K/V conv (fp32 x in, permuted weights -> coalesced out)
    dim3 gqkv(T_ / 128, 24, B_);
    qkvconv_kernel<<<gqkv, 128, QKV_SMEM>>>(x, wq5, wk5, wv, bq, bk, qp, kp, vp, qk_scale);

    // ---- attention (BM=256; 1D grid, heavy q-tiles first)
    attn_mma_kernel<<<256, 256, ATTN_SMEM>>>(qp, kp, vp, ph);

    // ---- output projection: split-K partials + reduce
    dim3 gp(T_ / 128, PSPLIT, B_);
    proj_partial_kernel<<<gp, 256, PROJ_SMEM>>>(ph, wu, pacc);
    proj_reduce_kernel<<<(B_ * T_ * KD_) / 256, 256>>>(pacc, bu, out);
}

// round 14
// speedup vs baseline: 1.1084x; 1.1084x over previous
#include <cuda_runtime.h>
#include <cuda_fp16.h>
#include <cstdint>
#include <cstddef>

// Problem constants
#define B_ 4
#define T_ 2048
#define KD_ 128
#define H_ 8
#define C_ 1024   // KD_*H_
#define PSPLIT 4

// Scratch (device globals; no allocation allowed)
__device__ __align__(256) __half g_Wq5[(size_t)5 * C_ * KD_];     // [tap][f(perm)][cin]
__device__ __align__(256) __half g_Wk5[(size_t)5 * C_ * KD_];
__device__ __align__(256) __half g_Wv [(size_t)C_ * KD_];         // [f(perm)][cin]
__device__ __align__(256) __half g_Wu [(size_t)KD_ * C_];         // [cout][f]
__device__ __align__(256) __half g_Qh [(size_t)32 * T_ * KD_];    // [b][t][f] == [m][t'][d]
__device__ __align__(256) __half g_Kh [(size_t)32 * T_ * KD_];
__device__ __align__(256) __half g_Vh [(size_t)32 * T_ * KD_];
__device__ __align__(256) __half g_Ph [(size_t)B_ * T_ * C_];     // attn out [b][t][f]
__device__ __align__(256) float  g_acc[(size_t)PSPLIT * B_ * T_ * KD_];  // proj partials

__device__ __forceinline__ uint32_t smem_to_u32(const void* p) {
    uint32_t a;
    asm("{ .reg .u64 t; cvta.to.shared.u64 t, %1; cvt.u32.u64 %0, t; }" : "=r"(a) : "l"(p));
    return a;
}

#define LDMATRIX_X4(r0, r1, r2, r3, addr) \
    asm volatile("ldmatrix.sync.aligned.m8n8.x4.shared.b16 {%0,%1,%2,%3}, [%4];" \
        : "=r"(r0), "=r"(r1), "=r"(r2), "=r"(r3) : "r"(addr))
#define LDMATRIX_X4_T(r0, r1, r2, r3, addr) \
    asm volatile("ldmatrix.sync.aligned.m8n8.x4.trans.shared.b16 {%0,%1,%2,%3}, [%4];" \
        : "=r"(r0), "=r"(r1), "=r"(r2), "=r"(r3) : "r"(addr))
#define MMA_16816(c, a, b0v, b1v) \
    asm volatile("mma.sync.aligned.m16n8k16.row.col.f32.f16.f16.f32 " \
        "{%0,%1,%2,%3},{%4,%5,%6,%7},{%8,%9},{%0,%1,%2,%3};" \
        : "+f"((c)[0]), "+f"((c)[1]), "+f"((c)[2]), "+f"((c)[3]) \
        : "r"((a)[0]), "r"((a)[1]), "r"((a)[2]), "r"((a)[3]), "r"(b0v), "r"(b1v))

#define CP_ASYNC16(dst, src) \
    asm volatile("cp.async.cg.shared.global [%0], [%1], 16;" :: "r"(dst), "l"(src))
#define CP_COMMIT() asm volatile("cp.async.commit_group;" ::: "memory")
template<int N> __device__ __forceinline__ void cp_wait() {
    asm volatile("cp.async.wait_group %0;" :: "n"(N) : "memory");
}

__device__ __forceinline__ float silu_f(float y) { return y / (1.0f + __expf(-y)); }

// ===========================================================================
// Weight prepack (x converted inside qkvconv). Wq/Wk/Wv cout rows PERMUTED:
// row f holds original channel c = ((f&127)<<3)|(f>>7)  (f = h*128 + k).
// ===========================================================================
#define N_W5 (5 * C_ * KD_)         // 655360
#define N_WV (C_ * KD_)             // 131072
#define N_WU (KD_ * C_)             // 131072
#define N_PACK (2 * N_W5 + N_WV + N_WU)

__global__ void pack_all_kernel(
    const float* __restrict__ Wq, const float* __restrict__ Wk,
    const float* __restrict__ Wv, const float* __restrict__ Wu,
    __half* __restrict__ wq5, __half* __restrict__ wk5,
    __half* __restrict__ wv, __half* __restrict__ wu)
{
    int i = blockIdx.x * 256 + threadIdx.x;
    if (i < N_W5) {
        int cin = i & 127, f = (i >> 7) & 1023, j = i >> 17;
        int c = ((f & 127) << 3) | (f >> 7);
        wq5[i] = __float2half(Wq[((c << 7) + cin) * 5 + j]);
        return;
    }
    i -= N_W5;
    if (i < N_W5) {
        int cin = i & 127, f = (i >> 7) & 1023, j = i >> 17;
        int c = ((f & 127) << 3) | (f >> 7);
        wk5[i] = __float2half(Wk[((c << 7) + cin) * 5 + j]);
        return;
    }
    i -= N_W5;
    if (i < N_WV) {
        int cin = i & 127, f = i >> 7;
        int c = ((f & 127) << 3) | (f >> 7);
        wv[i] = __float2half(Wv[(c << 7) + cin]);
        return;
    }
    i -= N_WV;
    if (i < N_WU) { wu[i] = __float2half(Wu[i]); }
}

// ===========================================================================
// Merged Q/K/V conv kernel. 128 threads / 4 warps, M=32 rows per warp.
// A loaded DIRECTLY from fp32 x (converted during smem fill; A loaded once).
// B double-buffered cp.async over taps; permuted weights -> coalesced stores.
// blockIdx.y: 0-7 Q tiles, 8-15 K tiles, 16-23 V tiles (1 tap, row off 8).
// ===========================================================================
#define QKV_SMEM (34816 + 2 * 32768)

__global__ void __launch_bounds__(128, 2) qkvconv_kernel(
    const float* __restrict__ X,
    const __half* __restrict__ Wq5, const __half* __restrict__ Wk5,
    const __half* __restrict__ Wv,
    const float* __restrict__ bq, const float* __restrict__ bk,
    __half* __restrict__ Qo, __half* __restrict__ Ko, __half* __restrict__ Vo,
    float qk_scale)
{
    extern __shared__ char smc[];
    const uint32_t sA  = smem_to_u32(smc);
    const uint32_t sB0 = sA + 34816;

    const int t0 = blockIdx.x * 128;
    const int cm = blockIdx.y;
    const int mat = cm >> 3;                 // 0=Q 1=K 2=V
    const int c0 = (cm & 7) * 128;           // f-tile base
    const int b  = blockIdx.z;
    const __half* Bw  = (mat == 0) ? Wq5 : (mat == 1) ? Wk5 : Wv;
    const float* bias = (mat == 0) ? bq  : (mat == 1) ? bk  : nullptr;
    __half* out       = (mat == 0) ? Qo  : (mat == 1) ? Ko  : Vo;
    const float scale = (mat == 2) ? 1.0f : qk_scale;
    const int ntaps   = (mat == 2) ? 1 : 5;

    const int tid = threadIdx.x, w = tid >> 5, l = tid & 31;
    const int mi = l >> 3;

    // ---- prefetch B tap 0 into buf 0 (32KB / 128 thr = 16 x 16B each)
    #pragma unroll
    for (int it = 0; it < 16; it++) {
        int idx = it * 128 + tid;
        int r = idx >> 4, cb = idx & 15;
        CP_ASYNC16(sB0 + r * 256 + ((cb ^ (r & 7)) << 4),
                   Bw + ((size_t)(c0 + r)) * 128 + cb * 8);
    }
    CP_COMMIT();

    // ---- load A rows t0-8 .. t0+127 (136 rows) from fp32 x, convert to fp16
    #pragma unroll
    for (int it = 0; it < 17; it++) {
        int idx = it * 128 + tid;
        if (idx < 136 * 16) {
            int r = idx >> 4, cb = idx & 15;
            int tg = t0 + r - 8;
            uint4 v = make_uint4(0u, 0u, 0u, 0u);
            if (tg >= 0 && tg < T_) {
                const float4* src = (const float4*)(X + ((size_t)b * T_ + tg) * 128);
                float4 f0 = src[cb * 2], f1 = src[cb * 2 + 1];
                __half2 h0 = __floats2half2_rn(f0.x, f0.y);
                __half2 h1 = __floats2half2_rn(f0.z, f0.w);
                __half2 h2 = __floats2half2_rn(f1.x, f1.y);
                __half2 h3 = __floats2half2_rn(f1.z, f1.w);
                v = make_uint4(*(uint32_t*)&h0, *(uint32_t*)&h1,
                               *(uint32_t*)&h2, *(uint32_t*)&h3);
            }
            *(uint4*)(smc + r * 256 + ((cb ^ (r & 7)) << 4)) = v;
        }
    }

    float cacc[2][16][4] = {};

    #pragma unroll 1
    for (int j = 0; j < ntaps; j++) {
        __syncthreads();   // prior compute done (protects buf (j+1)&1); A stores for j=0
        if (j + 1 < ntaps) {
            const uint32_t sBn = sB0 + ((j + 1) & 1) * 32768;
            #pragma unroll
            for (int it = 0; it < 16; it++) {
                int idx = it * 128 + tid;
                int r = idx >> 4, cb = idx & 15;
                CP_ASYNC16(sBn + r * 256 + ((cb ^ (r & 7)) << 4),
                           Bw + ((size_t)(j + 1) * C_ + c0 + r) * 128 + cb * 8);
            }
            CP_COMMIT();
            cp_wait<1>();
        } else {
            cp_wait<0>();
        }
        __syncthreads();

        const uint32_t sB = sB0 + (j & 1) * 32768;
        const int rowoff = (mat == 2) ? 8 : 2 * j;  // A row = out row + rowoff
        #pragma unroll
        for (int kc = 0; kc < 8; kc++) {
            uint32_t a4[2][4];
            #pragma unroll
            for (int rg = 0; rg < 2; rg++) {
                const int rr = w * 32 + rg * 16 + (mi & 1) * 8 + (l & 7) + rowoff;
                const int cba = kc * 2 + (mi >> 1);
                LDMATRIX_X4(a4[rg][0], a4[rg][1], a4[rg][2], a4[rg][3],
                            sA + rr * 256 + ((cba ^ (rr & 7)) << 4));
            }
            #pragma unroll
            for (int jn = 0; jn < 16; jn += 2) {
                const int nr = (jn + (mi >> 1)) * 8 + (l & 7);
                const int cbb = kc * 2 + (mi & 1);
                uint32_t b0, b1, b2, b3;
                LDMATRIX_X4(b0, b1, b2, b3, sB + nr * 256 + ((cbb ^ (nr & 7)) << 4));
                MMA_16816(cacc[0][jn],     a4[0], b0, b1);
                MMA_16816(cacc[0][jn + 1], a4[0], b2, b3);
                MMA_16816(cacc[1][jn],     a4[1], b0, b1);
                MMA_16816(cacc[1][jn + 1], a4[1], b2, b3);
            }
        }
    }

    // ---- epilogue: bias(perm) + silu + scale, COALESCED half2 stores [b][t][f]
    #pragma unroll
    for (int rg = 0; rg < 2; rg++) {
        const int tr0 = t0 + w * 32 + rg * 16 + (l >> 2);
        const int tr1 = tr0 + 8;
        #pragma unroll
        for (int jn = 0; jn < 16; jn++) {
            const int f = c0 + 8 * jn + 2 * (l & 3);
            float bv0 = 0.0f, bv1 = 0.0f;
            if (mat < 2) {
                const int co = ((f & 127) << 3) | (f >> 7);   // original channel
                bv0 = bias[co];
                bv1 = bias[co + 8];                            // f+1 -> k+1 -> c+8
            }
            float s00 = silu_f(cacc[rg][jn][0] + bv0) * scale;
            float s01 = silu_f(cacc[rg][jn][1] + bv1) * scale;
            float s10 = silu_f(cacc[rg][jn][2] + bv0) * scale;
            float s11 = silu_f(cacc[rg][jn][3] + bv1) * scale;
            *(__half2*)(out + ((size_t)b * T_ + tr0) * C_ + f) = __floats2half2_rn(s00, s01);
            *(__half2*)(out + ((size_t)b * T_ + tr1) * C_ + f) = __floats2half2_rn(s10, s11);
        }
    }
}

// ===========================================================================
// Projection with split-K: partial GEMM (no act) + reduce(bias+silu).
// Both K-chunks prefetched via cp.async at CTA start (2 groups, 128KB smem).
// ===========================================================================
#define PROJ_SMEM 131072

__global__ void __launch_bounds__(256, 1) proj_partial_kernel(
    const __half* __restrict__ A, const __half* __restrict__ Bw,
    float* __restrict__ part)
{
    extern __shared__ char smc[];
    const uint32_t sBase = smem_to_u32(smc);

    const int t0 = blockIdx.x * 128;
    const int sp = blockIdx.y;
    const int b  = blockIdx.z;
    const int tid = threadIdx.x, w = tid >> 5, l = tid & 31;
    const int mi = l >> 3;

    #pragma unroll
    for (int ch = 0; ch < 2; ch++) {
        const int cin0 = sp * 256 + ch * 128;
        const uint32_t sA = sBase + ch * 65536;
        const uint32_t sB = sA + 32768;
        #pragma unroll
        for (int it = 0; it < 8; it++) {
            int idx = it * 256 + tid;
            int r = idx >> 4, cb = idx & 15;
            int off = r * 256 + ((cb ^ (r & 7)) << 4);
            CP_ASYNC16(sA + off, A + ((size_t)b * T_ + t0 + r) * C_ + cin0 + cb * 8);
            CP_ASYNC16(sB + off, Bw + (size_t)r * C_ + cin0 + cb * 8);
        }
        CP_COMMIT();
    }

    float cacc[16][4] = {};

    #pragma unroll
    for (int ch = 0; ch < 2; ch++) {
        if (ch == 0) cp_wait<1>(); else cp_wait<0>();
        __syncthreads();
        const uint32_t sA = sBase + ch * 65536;
        const uint32_t sB = sA + 32768;
        #pragma unroll
        for (int kc = 0; kc < 8; kc++) {
            uint32_t a4[4];
            const int rr = w * 16 + (mi & 1) * 8 + (l & 7);
            const int cba = kc * 2 + (mi >> 1);
            LDMATRIX_X4(a4[0], a4[1], a4[2], a4[3],
                        sA + rr * 256 + ((cba ^ (rr & 7)) << 4));
            #pragma unroll
            for (int jn = 0; jn < 16; jn += 2) {
                const int nr = (jn + (mi >> 1)) * 8 + (l & 7);
                const int cbb = kc * 2 + (mi & 1);
                uint32_t b0, b1, b2, b3;
                LDMATRIX_X4(b0, b1, b2, b3, sB + nr * 256 + ((cbb ^ (nr & 7)) << 4));
                MMA_16816(cacc[jn],     a4, b0, b1);
                MMA_16816(cacc[jn + 1], a4, b2, b3);
            }
        }
    }

    const int tr0 = t0 + w * 16 + (l >> 2);
    const int tr1 = tr0 + 8;
    float* dst = part + (size_t)sp * (B_ * T_ * KD_);
    #pragma unroll
    for (int jn = 0; jn < 16; jn++) {
        const int c = 8 * jn + 2 * (l & 3);
        *(float2*)(dst + ((size_t)b * T_ + tr0) * KD_ + c) = make_float2(cacc[jn][0], cacc[jn][1]);
        *(float2*)(dst + ((size_t)b * T_ + tr1) * KD_ + c) = make_float2(cacc[jn][2], cacc[jn][3]);
    }
}

__global__ void proj_reduce_kernel(const float* __restrict__ part,
                                   const float* __restrict__ bu,
                                   float* __restrict__ out)
{
    const int i = blockIdx.x * 256 + threadIdx.x;   // over B*T*128
    const int c = i & 127;
    const int S = B_ * T_ * KD_;
    float s = part[i] + part[i + S] + part[i + 2 * S] + part[i + 3 * S];
    out[i] = silu_f(s + bu[c]);
}

// ===========================================================================
// Flash attention via mma.sync (R11 proven config). BM=128, 8 warps x 16
// rows. K/V loaded in PAIRS of 64-row s-tiles per cp.async group.
// Q/K carry sqrt(log2e) factor -> S in log2 domain; exp via ex2.f16x2.
// Smem: Q 32KB | buf0 [K 32KB | V 32KB] | buf1 [K 32KB | V 32KB] = 160KB.
// ===========================================================================
#define BM 128
#define BN 64
#define ATTN_SMEM (32768 + 2 * 65536)

__global__ void __launch_bounds__(256, 1)
attn_mma_kernel(const __half* __restrict__ Qb, const __half* __restrict__ Kb,
                const __half* __restrict__ Vb, __half* __restrict__ Ph)
{
    extern __shared__ char smc[];
    const uint32_t sQ = smem_to_u32(smc);

    const int tid = threadIdx.x, w = tid >> 5, l = tid & 31;
    const int bid = blockIdx.x;
    const int bi  = 15 - (bid >> 5);       // q-tile index, heavy (15) first
    const int m   = bid & 31;
    const int q0  = bi * BM;
    const size_t mbase = (size_t)m * T_ * KD_;
    const int npairs = bi + 1;             // (2*bi+2)/2 pairs of 64-row s-tiles

    // ---- prefetch pair 0 (128 K rows + 128 V rows) into buf 0
    {
        const __half* ks = Kb + mbase;
        const __half* vs = Vb + mbase;
        #pragma unroll
        for (int it = 0; it < 8; it++) {
            int idx = it * 256 + tid;
            int r = idx >> 4, cb = idx & 15;
            int off = r * 256 + ((cb ^ (r & 7)) << 4);
            CP_ASYNC16(sQ + 32768 + off,         ks + (size_t)r * KD_ + cb * 8);
            CP_ASYNC16(sQ + 32768 + 32768 + off, vs + (size_t)r * KD_ + cb * 8);
        }
        CP_COMMIT();
    }

    // ---- load Q tile [128 x 128] into swizzled smem
    {
        const uint4* src = (const uint4*)(Qb + mbase + (size_t)q0 * KD_);
        #pragma unroll
        for (int it = 0; it < 8; it++) {
            int idx = it * 256 + tid;
            int r = idx >> 4, cb = idx & 15;
            uint4 v = src[idx];
            *(uint4*)(smc + r * 256 + ((cb ^ (r & 7)) << 4)) = v;
        }
    }
    __syncthreads();

    // ---- extract Q A-frags
    uint32_t qa[8][4];
    {
        const int mi = l >> 3;
        const int rr = w * 16 + (mi & 1) * 8 + (l & 7);
        #pragma unroll
        for (int kc = 0; kc < 8; kc++) {
            const int cb = kc * 2 + (mi >> 1);
            LDMATRIX_X4(qa[kc][0], qa[kc][1], qa[kc][2], qa[kc][3],
                        sQ + rr * 256 + ((cb ^ (rr & 7)) << 4));
        }
    }

    float oacc[16][4] = {};
    float lsum0 = 0.0f, lsum1 = 0.0f;
    const int r0g = q0 + w * 16 + (l >> 2);
    const int r1g = r0g + 8;

    #pragma unroll 1
    for (int p = 0; p < npairs; p++) {
        __syncthreads();   // prior compute done (protects buf (p+1)&1)
        if (p + 1 < npairs) {
            const int s1 = (p + 1) * 128;
            const uint32_t base = sQ + 32768 + ((p + 1) & 1) * 65536;
            const __half* ks = Kb + mbase + (size_t)s1 * KD_;
            const __half* vs = Vb + mbase + (size_t)s1 * KD_;
            #pragma unroll
            for (int it = 0; it < 8; it++) {
                int idx = it * 256 + tid;
                int r = idx >> 4, cb = idx & 15;
                int off = r * 256 + ((cb ^ (r & 7)) << 4);
                CP_ASYNC16(base + off,         ks + (size_t)r * KD_ + cb * 8);
                CP_ASYNC16(base + 32768 + off, vs + (size_t)r * KD_ + cb * 8);
            }
            CP_COMMIT();
            cp_wait<1>();
        } else {
            cp_wait<0>();
        }
        __syncthreads();

        const uint32_t bufK = sQ + 32768 + (p & 1) * 65536;
        const uint32_t bufV = bufK + 32768;

        #pragma unroll
        for (int sub = 0; sub < 2; sub++) {
            const int s0 = p * 128 + sub * BN;
            const uint32_t sK = bufK + sub * 64 * 256;
            const uint32_t sV = bufV + sub * 64 * 256;

            // ---- S = Q K^T  (log2-domain logits)
            float sacc[8][4] = {};
            {
                const int mi = l >> 3;
                #pragma unroll
                for (int kc = 0; kc < 8; kc++) {
                    #pragma unroll
                    for (int j = 0; j < 8; j += 2) {
                        const int nr = (j + (mi >> 1)) * 8 + (l & 7);
                        const int cb = kc * 2 + (mi & 1);
                        uint32_t b0, b1, b2, b3;
                        LDMATRIX_X4(b0, b1, b2, b3, sK + nr * 256 + ((cb ^ (nr & 7)) << 4));
                        MMA_16816(sacc[j],     qa[kc], b0, b1);
                        MMA_16816(sacc[j + 1], qa[kc], b2, b3);
                    }
                }
            }

            // ---- mask + ex2.f16x2 -> P A-frags (one MUFU per 2 values)
            uint32_t pa[4][4];
            {
                const int cb0 = s0 + 2 * (l & 3);
                #pragma unroll
                for (int j = 0; j < 8; j++) {
                    const int c0 = cb0 + 8 * j, c1 = c0 + 1;
                    float m00 = (c0 <= r0g) ? sacc[j][0] : -60.0f;
                    float m01 = (c1 <= r0g) ? sacc[j][1] : -60.0f;
                    float m10 = (c0 <= r1g) ? sacc[j][2] : -60.0f;
                    float m11 = (c1 <= r1g) ? sacc[j][3] : -60.0f;
                    __half2 ha = __floats2half2_rn(m00, m01);
                    __half2 hb = __floats2half2_rn(m10, m11);
                    uint32_t ua, ub;
                    asm("ex2.approx.f16x2 %0, %1;" : "=r"(ua) : "r"(*(uint32_t*)&ha));
                    asm("ex2.approx.f16x2 %0, %1;" : "=r"(ub) : "r"(*(uint32_t*)&hb));
                    float2 fa = __half22float2(*(__half2*)&ua);
                    float2 fb = __half22float2(*(__half2*)&ub);
                    lsum0 += fa.x + fa.y;
                    lsum1 += fb.x + fb.y;
                    const int kc2 = j >> 1, hi = (j & 1) * 2;
                    pa[kc2][hi + 0] = ua;
                    pa[kc2][hi + 1] = ub;
                }
            }

            // ---- O += P V
            {
                const int mi = l >> 3;
                #pragma unroll
                for (int kc2 = 0; kc2 < 4; kc2++) {
                    #pragma unroll
                    for (int j = 0; j < 16; j += 2) {
                        const int sr = kc2 * 16 + (mi & 1) * 8 + (l & 7);
                        const int cb = j + (mi >> 1);
                        uint32_t b0, b1, b2, b3;
                        LDMATRIX_X4_T(b0, b1, b2, b3, sV + sr * 256 + ((cb ^ (sr & 7)) << 4));
                        MMA_16816(oacc[j],     pa[kc2], b0, b1);
                        MMA_16816(oacc[j + 1], pa[kc2], b2, b3);
                    }
                }
            }
        }
    }

    // ---- epilogue
    lsum0 += __shfl_xor_sync(0xffffffffu, lsum0, 1);
    lsum0 += __shfl_xor_sync(0xffffffffu, lsum0, 2);
    lsum1 += __shfl_xor_sync(0xffffffffu, lsum1, 1);
    lsum1 += __shfl_xor_sync(0xffffffffu, lsum1, 2);
    const float li0 = 1.0f / lsum0, li1 = 1.0f / lsum1;

    const int b = m >> 3, h = m & 7;
    __half* base0 = Ph + ((size_t)b * T_ + r0g) * C_ + h * KD_ + 2 * (l & 3);
    __half* base1 = Ph + ((size_t)b * T_ + r1g) * C_ + h * KD_ + 2 * (l & 3);
    #pragma unroll
    for (int j = 0; j < 16; j++) {
        *(__half2*)(base0 + 8 * j) = __floats2half2_rn(oacc[j][0] * li0, oacc[j][1] * li0);
        *(__half2*)(base1 + 8 * j) = __floats2half2_rn(oacc[j][2] * li1, oacc[j][3] * li1);
    }
}

// ===========================================================================
extern "C" void kernel_launch(void* const* d_in, const int* in_sizes, int n_in,
                              void* d_out, int out_size)
{
    const float* x  = (const float*)d_in[0];
    const float* Wq = (const float*)d_in[1];
    const float* bq = (const float*)d_in[2];
    const float* Wk = (const float*)d_in[3];
    const float* bk = (const float*)d_in[4];
    const float* Wv = (const float*)d_in[5];
    const float* Wu = (const float*)d_in[6];
    const float* bu = (const float*)d_in[7];
    float* out = (float*)d_out;

    __half *wq5, *wk5, *wv, *wu, *qp, *kp, *vp, *ph;
    float* pacc;
    cudaGetSymbolAddress((void**)&wq5,  g_Wq5);
    cudaGetSymbolAddress((void**)&wk5,  g_Wk5);
    cudaGetSymbolAddress((void**)&wv,   g_Wv);
    cudaGetSymbolAddress((void**)&wu,   g_Wu);
    cudaGetSymbolAddress((void**)&qp,   g_Qh);
    cudaGetSymbolAddress((void**)&kp,   g_Kh);
    cudaGetSymbolAddress((void**)&vp,   g_Vh);
    cudaGetSymbolAddress((void**)&ph,   g_Ph);
    cudaGetSymbolAddress((void**)&pacc, g_acc);

    cudaFuncSetAttribute(attn_mma_kernel, cudaFuncAttributeMaxDynamicSharedMemorySize, ATTN_SMEM);
    cudaFuncSetAttribute(qkvconv_kernel, cudaFuncAttributeMaxDynamicSharedMemorySize, QKV_SMEM);
    cudaFuncSetAttribute(proj_partial_kernel, cudaFuncAttributeMaxDynamicSharedMemorySize, PROJ_SMEM);

    // 1/128^0.25 * sqrt(log2(e))  -> S lands in log2 domain
    const float qk_scale = 0.3570958376f;

    // ---- weight prepack (x converted inside qkvconv)
    pack_all_kernel<<<N_PACK / 256, 256>>>(Wq, Wk, Wv, Wu, wq5, wk5, wv, wu);

    // ---- merged Q/K/V conv (fp32 x in, permuted weights -> coalesced out)
    dim3 gqkv(T_ / 128, 24, B_);
    qkvconv_kernel<<<gqkv, 128, QKV_SMEM>>>(x, wq5, wk5, wv, bq, bk, qp, kp, vp, qk_scale);

    // ---- attention (1D grid, heavy q-tiles first globally)
    attn_mma_kernel<<<512, 256, ATTN_SMEM>>>(qp, kp, vp, ph);

    // ---- output projection: split-K partials + reduce
    dim3 gp(T_ / 128, PSPLIT, B_);
    proj_partial_kernel<<<gp, 256, PROJ_SMEM>>>(ph, wu, pacc);
    proj_reduce_kernel<<<(B_ * T_ * KD_) / 256, 256>>>(pacc, bu, out);
}

// round 15
// speedup vs baseline: 1.1229x; 1.0131x over previous
#include <cuda_runtime.h>
#include <cuda_fp16.h>
#include <cstdint>
#include <cstddef>

// Problem constants
#define B_ 4
#define T_ 2048
#define KD_ 128
#define H_ 8
#define C_ 1024   // KD_*H_
#define PSPLIT 4

// Scratch (device globals; no allocation allowed)
__device__ __align__(256) __half g_xh [(size_t)B_ * T_ * KD_];    // x fp16 [b][t][cin]
__device__ __align__(256) __half g_Wq5[(size_t)5 * C_ * KD_];     // [tap][f(perm)][cin]
__device__ __align__(256) __half g_Wk5[(size_t)5 * C_ * KD_];
__device__ __align__(256) __half g_Wv [(size_t)C_ * KD_];         // [f(perm)][cin]
__device__ __align__(256) __half g_Wu [(size_t)KD_ * C_];         // [cout][f]
__device__ __align__(256) __half g_Qh [(size_t)32 * T_ * KD_];    // [b][t][f] == [m][t'][d]
__device__ __align__(256) __half g_Kh [(size_t)32 * T_ * KD_];
__device__ __align__(256) __half g_Vh [(size_t)32 * T_ * KD_];
__device__ __align__(256) __half g_Ph [(size_t)B_ * T_ * C_];     // attn out [b][t][f]
__device__ __align__(256) float  g_acc[(size_t)PSPLIT * B_ * T_ * KD_];  // proj partials

__device__ __forceinline__ uint32_t smem_to_u32(const void* p) {
    uint32_t a;
    asm("{ .reg .u64 t; cvta.to.shared.u64 t, %1; cvt.u32.u64 %0, t; }" : "=r"(a) : "l"(p));
    return a;
}

#define LDMATRIX_X4(r0, r1, r2, r3, addr) \
    asm volatile("ldmatrix.sync.aligned.m8n8.x4.shared.b16 {%0,%1,%2,%3}, [%4];" \
        : "=r"(r0), "=r"(r1), "=r"(r2), "=r"(r3) : "r"(addr))
#define LDMATRIX_X4_T(r0, r1, r2, r3, addr) \
    asm volatile("ldmatrix.sync.aligned.m8n8.x4.trans.shared.b16 {%0,%1,%2,%3}, [%4];" \
        : "=r"(r0), "=r"(r1), "=r"(r2), "=r"(r3) : "r"(addr))
#define MMA_16816(c, a, b0v, b1v) \
    asm volatile("mma.sync.aligned.m16n8k16.row.col.f32.f16.f16.f32 " \
        "{%0,%1,%2,%3},{%4,%5,%6,%7},{%8,%9},{%0,%1,%2,%3};" \
        : "+f"((c)[0]), "+f"((c)[1]), "+f"((c)[2]), "+f"((c)[3]) \
        : "r"((a)[0]), "r"((a)[1]), "r"((a)[2]), "r"((a)[3]), "r"(b0v), "r"(b1v))

#define CP_ASYNC16(dst, src) \
    asm volatile("cp.async.cg.shared.global [%0], [%1], 16;" :: "r"(dst), "l"(src))
#define CP_COMMIT() asm volatile("cp.async.commit_group;" ::: "memory")
template<int N> __device__ __forceinline__ void cp_wait() {
    asm volatile("cp.async.wait_group %0;" :: "n"(N) : "memory");
}

__device__ __forceinline__ float silu_f(float y) { return y / (1.0f + __expf(-y)); }

// ===========================================================================
// Fused prepack: x->fp16, Wq/Wk/Wv PERMUTED fp16 (row f holds channel
// c = ((f&127)<<3)|(f>>7), f = h*128+k), Wu fp16.
// ===========================================================================
#define N_X  (B_ * T_ * KD_)        // 1048576
#define N_W5 (5 * C_ * KD_)         // 655360
#define N_WV (C_ * KD_)             // 131072
#define N_WU (KD_ * C_)             // 131072
#define N_PACK (N_X + 2 * N_W5 + N_WV + N_WU)

__global__ void pack_all_kernel(
    const float* __restrict__ x, const float* __restrict__ Wq,
    const float* __restrict__ Wk, const float* __restrict__ Wv,
    const float* __restrict__ Wu,
    __half* __restrict__ xh, __half* __restrict__ wq5, __half* __restrict__ wk5,
    __half* __restrict__ wv, __half* __restrict__ wu)
{
    int i = blockIdx.x * 256 + threadIdx.x;
    if (i < N_X) { xh[i] = __float2half(x[i]); return; }
    i -= N_X;
    if (i < N_W5) {
        int cin = i & 127, f = (i >> 7) & 1023, j = i >> 17;
        int c = ((f & 127) << 3) | (f >> 7);
        wq5[i] = __float2half(Wq[((c << 7) + cin) * 5 + j]);
        return;
    }
    i -= N_W5;
    if (i < N_W5) {
        int cin = i & 127, f = (i >> 7) & 1023, j = i >> 17;
        int c = ((f & 127) << 3) | (f >> 7);
        wk5[i] = __float2half(Wk[((c << 7) + cin) * 5 + j]);
        return;
    }
    i -= N_W5;
    if (i < N_WV) {
        int cin = i & 127, f = i >> 7;
        int c = ((f & 127) << 3) | (f >> 7);
        wv[i] = __float2half(Wv[(c << 7) + cin]);
        return;
    }
    i -= N_WV;
    if (i < N_WU) { wu[i] = __float2half(Wu[i]); }
}

// ===========================================================================
// Merged Q/K/V conv kernel (R11 proven config). 128 threads / 4 warps,
// M=32 rows per warp. A (fp16, prepacked) resident; B double-buffered
// cp.async over taps; permuted weights -> coalesced half2 stores [b][t][f].
// blockIdx.y: 0-7 Q tiles, 8-15 K tiles, 16-23 V tiles (1 tap, row off 8).
// ===========================================================================
#define QKV_SMEM (34816 + 2 * 32768)

__global__ void __launch_bounds__(128, 2) qkvconv_kernel(
    const __half* __restrict__ A,
    const __half* __restrict__ Wq5, const __half* __restrict__ Wk5,
    const __half* __restrict__ Wv,
    const float* __restrict__ bq, const float* __restrict__ bk,
    __half* __restrict__ Qo, __half* __restrict__ Ko, __half* __restrict__ Vo,
    float qk_scale)
{
    extern __shared__ char smc[];
    const uint32_t sA  = smem_to_u32(smc);
    const uint32_t sB0 = sA + 34816;

    const int t0 = blockIdx.x * 128;
    const int cm = blockIdx.y;
    const int mat = cm >> 3;                 // 0=Q 1=K 2=V
    const int c0 = (cm & 7) * 128;           // f-tile base
    const int b  = blockIdx.z;
    const __half* Bw  = (mat == 0) ? Wq5 : (mat == 1) ? Wk5 : Wv;
    const float* bias = (mat == 0) ? bq  : (mat == 1) ? bk  : nullptr;
    __half* out       = (mat == 0) ? Qo  : (mat == 1) ? Ko  : Vo;
    const float scale = (mat == 2) ? 1.0f : qk_scale;
    const int ntaps   = (mat == 2) ? 1 : 5;

    const int tid = threadIdx.x, w = tid >> 5, l = tid & 31;
    const int mi = l >> 3;

    // ---- prefetch B tap 0 into buf 0 (32KB / 128 thr = 16 x 16B each)
    #pragma unroll
    for (int it = 0; it < 16; it++) {
        int idx = it * 128 + tid;
        int r = idx >> 4, cb = idx & 15;
        CP_ASYNC16(sB0 + r * 256 + ((cb ^ (r & 7)) << 4),
                   Bw + ((size_t)(c0 + r)) * 128 + cb * 8);
    }
    CP_COMMIT();

    // ---- load A rows t0-8 .. t0+127 (136 rows), guarded
    #pragma unroll
    for (int it = 0; it < 17; it++) {
        int idx = it * 128 + tid;
        if (idx < 136 * 16) {
            int r = idx >> 4, cb = idx & 15;
            int tg = t0 + r - 8;
            uint4 v = make_uint4(0u, 0u, 0u, 0u);
            if (tg >= 0 && tg < T_)
                v = *(const uint4*)(A + ((size_t)b * T_ + tg) * 128 + cb * 8);
            *(uint4*)(smc + r * 256 + ((cb ^ (r & 7)) << 4)) = v;
        }
    }

    float cacc[2][16][4] = {};

    #pragma unroll 1
    for (int j = 0; j < ntaps; j++) {
        __syncthreads();   // prior compute done (protects buf (j+1)&1); A stores for j=0
        if (j + 1 < ntaps) {
            const uint32_t sBn = sB0 + ((j + 1) & 1) * 32768;
            #pragma unroll
            for (int it = 0; it < 16; it++) {
                int idx = it * 128 + tid;
                int r = idx >> 4, cb = idx & 15;
                CP_ASYNC16(sBn + r * 256 + ((cb ^ (r & 7)) << 4),
                           Bw + ((size_t)(j + 1) * C_ + c0 + r) * 128 + cb * 8);
            }
            CP_COMMIT();
            cp_wait<1>();
        } else {
            cp_wait<0>();
        }
        __syncthreads();

        const uint32_t sB = sB0 + (j & 1) * 32768;
        const int rowoff = (mat == 2) ? 8 : 2 * j;  // A row = out row + rowoff
        #pragma unroll
        for (int kc = 0; kc < 8; kc++) {
            uint32_t a4[2][4];
            #pragma unroll
            for (int rg = 0; rg < 2; rg++) {
                const int rr = w * 32 + rg * 16 + (mi & 1) * 8 + (l & 7) + rowoff;
                const int cba = kc * 2 + (mi >> 1);
                LDMATRIX_X4(a4[rg][0], a4[rg][1], a4[rg][2], a4[rg][3],
                            sA + rr * 256 + ((cba ^ (rr & 7)) << 4));
            }
            #pragma unroll
            for (int jn = 0; jn < 16; jn += 2) {
                const int nr = (jn + (mi >> 1)) * 8 + (l & 7);
                const int cbb = kc * 2 + (mi & 1);
                uint32_t b0, b1, b2, b3;
                LDMATRIX_X4(b0, b1, b2, b3, sB + nr * 256 + ((cbb ^ (nr & 7)) << 4));
                MMA_16816(cacc[0][jn],     a4[0], b0, b1);
                MMA_16816(cacc[0][jn + 1], a4[0], b2, b3);
                MMA_16816(cacc[1][jn],     a4[1], b0, b1);
                MMA_16816(cacc[1][jn + 1], a4[1], b2, b3);
            }
        }
    }

    // ---- epilogue: bias(perm) + silu + scale, COALESCED half2 stores [b][t][f]
    #pragma unroll
    for (int rg = 0; rg < 2; rg++) {
        const int tr0 = t0 + w * 32 + rg * 16 + (l >> 2);
        const int tr1 = tr0 + 8;
        #pragma unroll
        for (int jn = 0; jn < 16; jn++) {
            const int f = c0 + 8 * jn + 2 * (l & 3);
            float bv0 = 0.0f, bv1 = 0.0f;
            if (mat < 2) {
                const int co = ((f & 127) << 3) | (f >> 7);   // original channel
                bv0 = bias[co];
                bv1 = bias[co + 8];                            // f+1 -> k+1 -> c+8
            }
            float s00 = silu_f(cacc[rg][jn][0] + bv0) * scale;
            float s01 = silu_f(cacc[rg][jn][1] + bv1) * scale;
            float s10 = silu_f(cacc[rg][jn][2] + bv0) * scale;
            float s11 = silu_f(cacc[rg][jn][3] + bv1) * scale;
            *(__half2*)(out + ((size_t)b * T_ + tr0) * C_ + f) = __floats2half2_rn(s00, s01);
            *(__half2*)(out + ((size_t)b * T_ + tr1) * C_ + f) = __floats2half2_rn(s10, s11);
        }
    }
}

// ===========================================================================
// Projection with split-K: partial GEMM (no act) + reduce(bias+silu).
// Both K-chunks prefetched via cp.async at CTA start (2 groups, 128KB smem).
// ===========================================================================
#define PROJ_SMEM 131072

__global__ void __launch_bounds__(256, 1) proj_partial_kernel(
    const __half* __restrict__ A, const __half* __restrict__ Bw,
    float* __restrict__ part)
{
    extern __shared__ char smc[];
    const uint32_t sBase = smem_to_u32(smc);

    const int t0 = blockIdx.x * 128;
    const int sp = blockIdx.y;
    const int b  = blockIdx.z;
    const int tid = threadIdx.x, w = tid >> 5, l = tid & 31;
    const int mi = l >> 3;

    #pragma unroll
    for (int ch = 0; ch < 2; ch++) {
        const int cin0 = sp * 256 + ch * 128;
        const uint32_t sA = sBase + ch * 65536;
        const uint32_t sB = sA + 32768;
        #pragma unroll
        for (int it = 0; it < 8; it++) {
            int idx = it * 256 + tid;
            int r = idx >> 4, cb = idx & 15;
            int off = r * 256 + ((cb ^ (r & 7)) << 4);
            CP_ASYNC16(sA + off, A + ((size_t)b * T_ + t0 + r) * C_ + cin0 + cb * 8);
            CP_ASYNC16(sB + off, Bw + (size_t)r * C_ + cin0 + cb * 8);
        }
        CP_COMMIT();
    }

    float cacc[16][4] = {};

    #pragma unroll
    for (int ch = 0; ch < 2; ch++) {
        if (ch == 0) cp_wait<1>(); else cp_wait<0>();
        __syncthreads();
        const uint32_t sA = sBase + ch * 65536;
        const uint32_t sB = sA + 32768;
        #pragma unroll
        for (int kc = 0; kc < 8; kc++) {
            uint32_t a4[4];
            const int rr = w * 16 + (mi & 1) * 8 + (l & 7);
            const int cba = kc * 2 + (mi >> 1);
            LDMATRIX_X4(a4[0], a4[1], a4[2], a4[3],
                        sA + rr * 256 + ((cba ^ (rr & 7)) << 4));
            #pragma unroll
            for (int jn = 0; jn < 16; jn += 2) {
                const int nr = (jn + (mi >> 1)) * 8 + (l & 7);
                const int cbb = kc * 2 + (mi & 1);
                uint32_t b0, b1, b2, b3;
                LDMATRIX_X4(b0, b1, b2, b3, sB + nr * 256 + ((cbb ^ (nr & 7)) << 4));
                MMA_16816(cacc[jn],     a4, b0, b1);
                MMA_16816(cacc[jn + 1], a4, b2, b3);
            }
        }
    }

    const int tr0 = t0 + w * 16 + (l >> 2);
    const int tr1 = tr0 + 8;
    float* dst = part + (size_t)sp * (B_ * T_ * KD_);
    #pragma unroll
    for (int jn = 0; jn < 16; jn++) {
        const int c = 8 * jn + 2 * (l & 3);
        *(float2*)(dst + ((size_t)b * T_ + tr0) * KD_ + c) = make_float2(cacc[jn][0], cacc[jn][1]);
        *(float2*)(dst + ((size_t)b * T_ + tr1) * KD_ + c) = make_float2(cacc[jn][2], cacc[jn][3]);
    }
}

__global__ void proj_reduce_kernel(const float* __restrict__ part,
                                   const float* __restrict__ bu,
                                   float* __restrict__ out)
{
    const int i = blockIdx.x * 256 + threadIdx.x;   // over B*T*128
    const int c = i & 127;
    const int S = B_ * T_ * KD_;
    float s = part[i] + part[i + S] + part[i + 2 * S] + part[i + 3 * S];
    out[i] = silu_f(s + bu[c]);
}

// ===========================================================================
// Flash attention via mma.sync. BM=128, 8 warps x 16 rows. K/V loaded in
// PAIRS of 64-row s-tiles, TRIPLE-buffered cp.async -> ONE barrier per pair:
// buf (p+1)%3 written at iter p was last read at compute(p-2), ordered by
// barrier B(p-1). Q/K carry sqrt(log2e) -> log2-domain S; exp via ex2.f16x2.
// Smem: Q 32KB | 3 x [K 32KB | V 32KB] = 229376 bytes.
// ===========================================================================
#define BM 128
#define BN 64
#define ATTN_SMEM (32768 + 3 * 65536)

__global__ void __launch_bounds__(256, 1)
attn_mma_kernel(const __half* __restrict__ Qb, const __half* __restrict__ Kb,
                const __half* __restrict__ Vb, __half* __restrict__ Ph)
{
    extern __shared__ char smc[];
    const uint32_t sQ = smem_to_u32(smc);

    const int tid = threadIdx.x, w = tid >> 5, l = tid & 31;
    const int bid = blockIdx.x;
    const int bi  = 15 - (bid >> 5);       // q-tile index, heavy (15) first
    const int m   = bid & 31;
    const int q0  = bi * BM;
    const size_t mbase = (size_t)m * T_ * KD_;
    const int npairs = bi + 1;             // pairs of 64-row s-tiles (128 rows each)

    // ---- prefetch pair 0 (128 K rows + 128 V rows) into buf 0
    {
        const __half* ks = Kb + mbase;
        const __half* vs = Vb + mbase;
        #pragma unroll
        for (int it = 0; it < 8; it++) {
            int idx = it * 256 + tid;
            int r = idx >> 4, cb = idx & 15;
            int off = r * 256 + ((cb ^ (r & 7)) << 4);
            CP_ASYNC16(sQ + 32768 + off,         ks + (size_t)r * KD_ + cb * 8);
            CP_ASYNC16(sQ + 32768 + 32768 + off, vs + (size_t)r * KD_ + cb * 8);
        }
        CP_COMMIT();
    }

    // ---- load Q tile [128 x 128] into swizzled smem
    {
        const uint4* src = (const uint4*)(Qb + mbase + (size_t)q0 * KD_);
        #pragma unroll
        for (int it = 0; it < 8; it++) {
            int idx = it * 256 + tid;
            int r = idx >> 4, cb = idx & 15;
            uint4 v = src[idx];
            *(uint4*)(smc + r * 256 + ((cb ^ (r & 7)) << 4)) = v;
        }
    }
    __syncthreads();

    // ---- extract Q A-frags
    uint32_t qa[8][4];
    {
        const int mi = l >> 3;
        const int rr = w * 16 + (mi & 1) * 8 + (l & 7);
        #pragma unroll
        for (int kc = 0; kc < 8; kc++) {
            const int cb = kc * 2 + (mi >> 1);
            LDMATRIX_X4(qa[kc][0], qa[kc][1], qa[kc][2], qa[kc][3],
                        sQ + rr * 256 + ((cb ^ (rr & 7)) << 4));
        }
    }

    float oacc[16][4] = {};
    float lsum0 = 0.0f, lsum1 = 0.0f;
    const int r0g = q0 + w * 16 + (l >> 2);
    const int r1g = r0g + 8;

    int bufn = 0;   // (p+1)%3 tracker for next-issue buffer
    #pragma unroll 1
    for (int p = 0; p < npairs; p++) {
        bufn = (bufn == 2) ? 0 : bufn + 1;   // (p+1)%3
        if (p + 1 < npairs) {
            const int s1 = (p + 1) * 128;
            const uint32_t base = sQ + 32768 + bufn * 65536;
            const __half* ks = Kb + mbase + (size_t)s1 * KD_;
            const __half* vs = Vb + mbase + (size_t)s1 * KD_;
            #pragma unroll
            for (int it = 0; it < 8; it++) {
                int idx = it * 256 + tid;
                int r = idx >> 4, cb = idx & 15;
                int off = r * 256 + ((cb ^ (r & 7)) << 4);
                CP_ASYNC16(base + off,         ks + (size_t)r * KD_ + cb * 8);
                CP_ASYNC16(base + 32768 + off, vs + (size_t)r * KD_ + cb * 8);
            }
            CP_COMMIT();
            cp_wait<1>();
        } else {
            cp_wait<0>();
        }
        __syncthreads();   // single barrier: visibility of pair p + orders buf reuse

        const int bufp = (bufn == 0) ? 2 : bufn - 1;   // p%3
        const uint32_t bufK = sQ + 32768 + bufp * 65536;
        const uint32_t bufV = bufK + 32768;

        #pragma unroll
        for (int sub = 0; sub < 2; sub++) {
            const int s0 = p * 128 + sub * BN;
            const uint32_t sK = bufK + sub * 64 * 256;
            const uint32_t sV = bufV + sub * 64 * 256;

            // ---- S = Q K^T  (log2-domain logits)
            float sacc[8][4] = {};
            {
                const int mi = l >> 3;
                #pragma unroll
                for (int kc = 0; kc < 8; kc++) {
                    #pragma unroll
                    for (int j = 0; j < 8; j += 2) {
                        const int nr = (j + (mi >> 1)) * 8 + (l & 7);
                        const int cb = kc * 2 + (mi & 1);
                        uint32_t b0, b1, b2, b3;
                        LDMATRIX_X4(b0, b1, b2, b3, sK + nr * 256 + ((cb ^ (nr & 7)) << 4));
                        MMA_16816(sacc[j],     qa[kc], b0, b1);
                        MMA_16816(sacc[j + 1], qa[kc], b2, b3);
                    }
                }
            }

            // ---- mask + ex2.f16x2 -> P A-frags (one MUFU per 2 values)
            uint32_t pa[4][4];
            {
                const int cb0 = s0 + 2 * (l & 3);
                #pragma unroll
                for (int j = 0; j < 8; j++) {
                    const int c0 = cb0 + 8 * j, c1 = c0 + 1;
                    float m00 = (c0 <= r0g) ? sacc[j][0] : -60.0f;
                    float m01 = (c1 <= r0g) ? sacc[j][1] : -60.0f;
                    float m10 = (c0 <= r1g) ? sacc[j][2] : -60.0f;
                    float m11 = (c1 <= r1g) ? sacc[j][3] : -60.0f;
                    __half2 ha = __floats2half2_rn(m00, m01);
                    __half2 hb = __floats2half2_rn(m10, m11);
                    uint32_t ua, ub;
                    asm("ex2.approx.f16x2 %0, %1;" : "=r"(ua) : "r"(*(uint32_t*)&ha));
                    asm("ex2.approx.f16x2 %0, %1;" : "=r"(ub) : "r"(*(uint32_t*)&hb));
                    float2 fa = __half22float2(*(__half2*)&ua);
                    float2 fb = __half22float2(*(__half2*)&ub);
                    lsum0 += fa.x + fa.y;
                    lsum1 += fb.x + fb.y;
                    const int kc2 = j >> 1, hi = (j & 1) * 2;
                    pa[kc2][hi + 0] = ua;
                    pa[kc2][hi + 1] = ub;
                }
            }

            // ---- O += P V
            {
                const int mi = l >> 3;
                #pragma unroll
                for (int kc2 = 0; kc2 < 4; kc2++) {
                    #pragma unroll
                    for (int j = 0; j < 16; j += 2) {
                        const int sr = kc2 * 16 + (mi & 1) * 8 + (l & 7);
                        const int cb = j + (mi >> 1);
                        uint32_t b0, b1, b2, b3;
                        LDMATRIX_X4_T(b0, b1, b2, b3, sV + sr * 256 + ((cb ^ (sr & 7)) << 4));
                        MMA_16816(oacc[j],     pa[kc2], b0, b1);
                        MMA_16816(oacc[j + 1], pa[kc2], b2, b3);
                    }
                }
            }
        }
    }

    // ---- epilogue
    lsum0 += __shfl_xor_sync(0xffffffffu, lsum0, 1);
    lsum0 += __shfl_xor_sync(0xffffffffu, lsum0, 2);
    lsum1 += __shfl_xor_sync(0xffffffffu, lsum1, 1);
    lsum1 += __shfl_xor_sync(0xffffffffu, lsum1, 2);
    const float li0 = 1.0f / lsum0, li1 = 1.0f / lsum1;

    const int b = m >> 3, h = m & 7;
    __half* base0 = Ph + ((size_t)b * T_ + r0g) * C_ + h * KD_ + 2 * (l & 3);
    __half* base1 = Ph + ((size_t)b * T_ + r1g) * C_ + h * KD_ + 2 * (l & 3);
    #pragma unroll
    for (int j = 0; j < 16; j++) {
        *(__half2*)(base0 + 8 * j) = __floats2half2_rn(oacc[j][0] * li0, oacc[j][1] * li0);
        *(__half2*)(base1 + 8 * j) = __floats2half2_rn(oacc[j][2] * li1, oacc[j][3] * li1);
    }
}

// ===========================================================================
extern "C" void kernel_launch(void* const* d_in, const int* in_sizes, int n_in,
                              void* d_out, int out_size)
{
    const float* x  = (const float*)d_in[0];
    const float* Wq = (const float*)d_in[1];
    const float* bq = (const float*)d_in[2];
    const float* Wk = (const float*)d_in[3];
    const float* bk = (const float*)d_in[4];
    const float* Wv = (const float*)d_in[5];
    const float* Wu = (const float*)d_in[6];
    const float* bu = (const float*)d_in[7];
    float* out = (float*)d_out;

    __half *xh, *wq5, *wk5, *wv, *wu, *qp, *kp, *vp, *ph;
    float* pacc;
    cudaGetSymbolAddress((void**)&xh,   g_xh);
    cudaGetSymbolAddress((void**)&wq5,  g_Wq5);
    cudaGetSymbolAddress((void**)&wk5,  g_Wk5);
    cudaGetSymbolAddress((void**)&wv,   g_Wv);
    cudaGetSymbolAddress((void**)&wu,   g_Wu);
    cudaGetSymbolAddress((void**)&qp,   g_Qh);
    cudaGetSymbolAddress((void**)&kp,   g_Kh);
    cudaGetSymbolAddress((void**)&vp,   g_Vh);
    cudaGetSymbolAddress((void**)&ph,   g_Ph);
    cudaGetSymbolAddress((void**)&pacc, g_acc);

    cudaFuncSetAttribute(attn_mma_kernel, cudaFuncAttributeMaxDynamicSharedMemorySize, ATTN_SMEM);
    cudaFuncSetAttribute(qkvconv_kernel, cudaFuncAttributeMaxDynamicSharedMemorySize, QKV_SMEM);
    cudaFuncSetAttribute(proj_partial_kernel, cudaFuncAttributeMaxDynamicSharedMemorySize, PROJ_SMEM);

    // 1/128^0.25 * sqrt(log2(e))  -> S lands in log2 domain
    const float qk_scale = 0.3570958376f;

    // ---- fused prepack (x + weights, 1 launch)
    pack_all_kernel<<<N_PACK / 256, 256>>>(x, Wq, Wk, Wv, Wu, xh, wq5, wk5, wv, wu);

    // ---- merged Q/K/V conv (fp16 A, permuted weights -> coalesced out)
    dim3 gqkv(T_ / 128, 24, B_);
    qkvconv_kernel<<<gqkv, 128, QKV_SMEM>>>(xh, wq5, wk5, wv, bq, bk, qp, kp, vp, qk_scale);

    // ---- attention (1D grid, heavy q-tiles first; triple-buffered K/V)
    attn_mma_kernel<<<512, 256, ATTN_SMEM>>>(qp, kp, vp, ph);

    // ---- output projection: split-K partials + reduce
    dim3 gp(T_ / 128, PSPLIT, B_);
    proj_partial_kernel<<<gp, 256, PROJ_SMEM>>>(ph, wu, pacc);
    proj_reduce_kernel<<<(B_ * T_ * KD_) / 256, 256>>>(pacc, bu, out);
}

// round 16
// speedup vs baseline: 1.1571x; 1.0304x over previous
#include <cuda_runtime.h>
#include <cuda_fp16.h>
#include <cstdint>
#include <cstddef>

// Problem constants
#define B_ 4
#define T_ 2048
#define KD_ 128
#define H_ 8
#define C_ 1024   // KD_*H_
#define PSPLIT 4
#define CKD (C_ * KD_)   // 131072

// Scratch (device globals; no allocation allowed)
__device__ __align__(256) __half g_xh [(size_t)B_ * T_ * KD_];    // x fp16 [b][t][cin]
__device__ __align__(256) __half g_Wq5[(size_t)5 * CKD];          // [tap][f(perm)][cin]
__device__ __align__(256) __half g_Wk5[(size_t)5 * CKD];
__device__ __align__(256) __half g_Wv [(size_t)CKD];              // [f(perm)][cin]
__device__ __align__(256) __half g_Wu [(size_t)KD_ * C_];         // [cout][f]
__device__ __align__(256) __half g_Qh [(size_t)32 * T_ * KD_];    // [b][t][f] == [m][t'][d]
__device__ __align__(256) __half g_Kh [(size_t)32 * T_ * KD_];
__device__ __align__(256) __half g_Vh [(size_t)32 * T_ * KD_];
__device__ __align__(256) __half g_Ph [(size_t)B_ * T_ * C_];     // attn out [b][t][f]
__device__ __align__(256) float  g_acc[(size_t)PSPLIT * B_ * T_ * KD_];  // proj partials

__device__ __forceinline__ uint32_t smem_to_u32(const void* p) {
    uint32_t a;
    asm("{ .reg .u64 t; cvta.to.shared.u64 t, %1; cvt.u32.u64 %0, t; }" : "=r"(a) : "l"(p));
    return a;
}

#define LDMATRIX_X4(r0, r1, r2, r3, addr) \
    asm volatile("ldmatrix.sync.aligned.m8n8.x4.shared.b16 {%0,%1,%2,%3}, [%4];" \
        : "=r"(r0), "=r"(r1), "=r"(r2), "=r"(r3) : "r"(addr))
#define LDMATRIX_X4_T(r0, r1, r2, r3, addr) \
    asm volatile("ldmatrix.sync.aligned.m8n8.x4.trans.shared.b16 {%0,%1,%2,%3}, [%4];" \
        : "=r"(r0), "=r"(r1), "=r"(r2), "=r"(r3) : "r"(addr))
#define MMA_16816(c, a, b0v, b1v) \
    asm volatile("mma.sync.aligned.m16n8k16.row.col.f32.f16.f16.f32 " \
        "{%0,%1,%2,%3},{%4,%5,%6,%7},{%8,%9},{%0,%1,%2,%3};" \
        : "+f"((c)[0]), "+f"((c)[1]), "+f"((c)[2]), "+f"((c)[3]) \
        : "r"((a)[0]), "r"((a)[1]), "r"((a)[2]), "r"((a)[3]), "r"(b0v), "r"(b1v))

#define CP_ASYNC16(dst, src) \
    asm volatile("cp.async.cg.shared.global [%0], [%1], 16;" :: "r"(dst), "l"(src))
#define CP_COMMIT() asm volatile("cp.async.commit_group;" ::: "memory")
template<int N> __device__ __forceinline__ void cp_wait() {
    asm volatile("cp.async.wait_group %0;" :: "n"(N) : "memory");
}

__device__ __forceinline__ float silu_f(float y) { return y / (1.0f + __expf(-y)); }

// ===========================================================================
// Fused prepack: x->fp16 (per element); Wq/Wk 5-tap per-thread (coalesced
// reads AND per-plane coalesced writes); Wv permuted; Wu plain.
// Permutation: row f holds channel c; f = ((c&7)<<7)|(c>>3).
// ===========================================================================
#define N_X  (B_ * T_ * KD_)        // 1048576
#define N_PACK (N_X + 2 * CKD + CKD + KD_ * C_)   // 1572864

__global__ void pack_all_kernel(
    const float* __restrict__ x, const float* __restrict__ Wq,
    const float* __restrict__ Wk, const float* __restrict__ Wv,
    const float* __restrict__ Wu,
    __half* __restrict__ xh, __half* __restrict__ wq5, __half* __restrict__ wk5,
    __half* __restrict__ wv, __half* __restrict__ wu)
{
    int i = blockIdx.x * 256 + threadIdx.x;
    if (i < N_X) { xh[i] = __float2half(x[i]); return; }
    i -= N_X;
    if (i < CKD) {
        // thread handles all 5 taps of (c, cin)
        const int c = i >> 7, cin = i & 127;
        const int f = ((c & 7) << 7) | (c >> 3);
        const float* src = Wq + (size_t)i * 5;
        #pragma unroll
        for (int j = 0; j < 5; j++)
            wq5[(size_t)j * CKD + (f << 7) + cin] = __float2half(src[j]);
        return;
    }
    i -= CKD;
    if (i < CKD) {
        const int c = i >> 7, cin = i & 127;
        const int f = ((c & 7) << 7) | (c >> 3);
        const float* src = Wk + (size_t)i * 5;
        #pragma unroll
        for (int j = 0; j < 5; j++)
            wk5[(size_t)j * CKD + (f << 7) + cin] = __float2half(src[j]);
        return;
    }
    i -= CKD;
    if (i < CKD) {
        int cin = i & 127, f = i >> 7;
        int c = ((f & 127) << 3) | (f >> 7);
        wv[i] = __float2half(Wv[(c << 7) + cin]);
        return;
    }
    i -= CKD;
    if (i < KD_ * C_) { wu[i] = __float2half(Wu[i]); }
}

// ===========================================================================
// Merged Q/K/V conv kernel. 128 threads / 4 warps, M=32 rows per warp.
// A (fp16, prepacked) loaded via guarded cp.async (group 0); B tap buffers
// double-buffered cp.async; permuted weights -> coalesced half2 stores.
// blockIdx.y: 0-7 Q tiles, 8-15 K tiles, 16-23 V tiles (1 tap, row off 8).
// ===========================================================================
#define QKV_SMEM (34816 + 2 * 32768)

__global__ void __launch_bounds__(128, 2) qkvconv_kernel(
    const __half* __restrict__ A,
    const __half* __restrict__ Wq5, const __half* __restrict__ Wk5,
    const __half* __restrict__ Wv,
    const float* __restrict__ bq, const float* __restrict__ bk,
    __half* __restrict__ Qo, __half* __restrict__ Ko, __half* __restrict__ Vo,
    float qk_scale)
{
    extern __shared__ char smc[];
    const uint32_t sA  = smem_to_u32(smc);
    const uint32_t sB0 = sA + 34816;

    const int t0 = blockIdx.x * 128;
    const int cm = blockIdx.y;
    const int mat = cm >> 3;                 // 0=Q 1=K 2=V
    const int c0 = (cm & 7) * 128;           // f-tile base
    const int b  = blockIdx.z;
    const __half* Bw  = (mat == 0) ? Wq5 : (mat == 1) ? Wk5 : Wv;
    const float* bias = (mat == 0) ? bq  : (mat == 1) ? bk  : nullptr;
    __half* out       = (mat == 0) ? Qo  : (mat == 1) ? Ko  : Vo;
    const float scale = (mat == 2) ? 1.0f : qk_scale;
    const int ntaps   = (mat == 2) ? 1 : 5;

    const int tid = threadIdx.x, w = tid >> 5, l = tid & 31;
    const int mi = l >> 3;

    // ---- group 0: A rows t0-8 .. t0+127 (136 rows) via guarded cp.async
    #pragma unroll
    for (int it = 0; it < 17; it++) {
        int idx = it * 128 + tid;
        if (idx < 136 * 16) {
            int r = idx >> 4, cb = idx & 15;
            int tg = t0 + r - 8;
            uint32_t dst = sA + r * 256 + ((cb ^ (r & 7)) << 4);
            if (tg >= 0)
                CP_ASYNC16(dst, A + ((size_t)b * T_ + tg) * 128 + cb * 8);
            else
                *(uint4*)(smc + (dst - sA)) = make_uint4(0u, 0u, 0u, 0u);
        }
    }
    CP_COMMIT();

    // ---- group 1: B tap 0 into buf 0
    #pragma unroll
    for (int it = 0; it < 16; it++) {
        int idx = it * 128 + tid;
        int r = idx >> 4, cb = idx & 15;
        CP_ASYNC16(sB0 + r * 256 + ((cb ^ (r & 7)) << 4),
                   Bw + ((size_t)(c0 + r)) * 128 + cb * 8);
    }
    CP_COMMIT();

    float cacc[2][16][4] = {};

    #pragma unroll 1
    for (int j = 0; j < ntaps; j++) {
        __syncthreads();   // prior compute done (protects buf (j+1)&1)
        if (j + 1 < ntaps) {
            const uint32_t sBn = sB0 + ((j + 1) & 1) * 32768;
            #pragma unroll
            for (int it = 0; it < 16; it++) {
                int idx = it * 128 + tid;
                int r = idx >> 4, cb = idx & 15;
                CP_ASYNC16(sBn + r * 256 + ((cb ^ (r & 7)) << 4),
                           Bw + ((size_t)(j + 1) * C_ + c0 + r) * 128 + cb * 8);
            }
            CP_COMMIT();
            cp_wait<1>();   // A + taps 0..j complete; tap j+1 may fly
        } else {
            cp_wait<0>();
        }
        __syncthreads();

        const uint32_t sB = sB0 + (j & 1) * 32768;
        const int rowoff = (mat == 2) ? 8 : 2 * j;  // A row = out row + rowoff
        #pragma unroll
        for (int kc = 0; kc < 8; kc++) {
            uint32_t a4[2][4];
            #pragma unroll
            for (int rg = 0; rg < 2; rg++) {
                const int rr = w * 32 + rg * 16 + (mi & 1) * 8 + (l & 7) + rowoff;
                const int cba = kc * 2 + (mi >> 1);
                LDMATRIX_X4(a4[rg][0], a4[rg][1], a4[rg][2], a4[rg][3],
                            sA + rr * 256 + ((cba ^ (rr & 7)) << 4));
            }
            #pragma unroll
            for (int jn = 0; jn < 16; jn += 2) {
                const int nr = (jn + (mi >> 1)) * 8 + (l & 7);
                const int cbb = kc * 2 + (mi & 1);
                uint32_t b0, b1, b2, b3;
                LDMATRIX_X4(b0, b1, b2, b3, sB + nr * 256 + ((cbb ^ (nr & 7)) << 4));
                MMA_16816(cacc[0][jn],     a4[0], b0, b1);
                MMA_16816(cacc[0][jn + 1], a4[0], b2, b3);
                MMA_16816(cacc[1][jn],     a4[1], b0, b1);
                MMA_16816(cacc[1][jn + 1], a4[1], b2, b3);
            }
        }
    }

    // ---- epilogue: bias(perm) + silu + scale, COALESCED half2 stores [b][t][f]
    #pragma unroll
    for (int rg = 0; rg < 2; rg++) {
        const int tr0 = t0 + w * 32 + rg * 16 + (l >> 2);
        const int tr1 = tr0 + 8;
        #pragma unroll
        for (int jn = 0; jn < 16; jn++) {
            const int f = c0 + 8 * jn + 2 * (l & 3);
            float bv0 = 0.0f, bv1 = 0.0f;
            if (mat < 2) {
                const int co = ((f & 127) << 3) | (f >> 7);   // original channel
                bv0 = bias[co];
                bv1 = bias[co + 8];                            // f+1 -> k+1 -> c+8
            }
            float s00 = silu_f(cacc[rg][jn][0] + bv0) * scale;
            float s01 = silu_f(cacc[rg][jn][1] + bv1) * scale;
            float s10 = silu_f(cacc[rg][jn][2] + bv0) * scale;
            float s11 = silu_f(cacc[rg][jn][3] + bv1) * scale;
            *(__half2*)(out + ((size_t)b * T_ + tr0) * C_ + f) = __floats2half2_rn(s00, s01);
            *(__half2*)(out + ((size_t)b * T_ + tr1) * C_ + f) = __floats2half2_rn(s10, s11);
        }
    }
}

// ===========================================================================
// Projection with split-K: partial GEMM (no act) + vectorized reduce.
// ===========================================================================
#define PROJ_SMEM 131072

__global__ void __launch_bounds__(256, 1) proj_partial_kernel(
    const __half* __restrict__ A, const __half* __restrict__ Bw,
    float* __restrict__ part)
{
    extern __shared__ char smc[];
    const uint32_t sBase = smem_to_u32(smc);

    const int t0 = blockIdx.x * 128;
    const int sp = blockIdx.y;
    const int b  = blockIdx.z;
    const int tid = threadIdx.x, w = tid >> 5, l = tid & 31;
    const int mi = l >> 3;

    #pragma unroll
    for (int ch = 0; ch < 2; ch++) {
        const int cin0 = sp * 256 + ch * 128;
        const uint32_t sA = sBase + ch * 65536;
        const uint32_t sB = sA + 32768;
        #pragma unroll
        for (int it = 0; it < 8; it++) {
            int idx = it * 256 + tid;
            int r = idx >> 4, cb = idx & 15;
            int off = r * 256 + ((cb ^ (r & 7)) << 4);
            CP_ASYNC16(sA + off, A + ((size_t)b * T_ + t0 + r) * C_ + cin0 + cb * 8);
            CP_ASYNC16(sB + off, Bw + (size_t)r * C_ + cin0 + cb * 8);
        }
        CP_COMMIT();
    }

    float cacc[16][4] = {};

    #pragma unroll
    for (int ch = 0; ch < 2; ch++) {
        if (ch == 0) cp_wait<1>(); else cp_wait<0>();
        __syncthreads();
        const uint32_t sA = sBase + ch * 65536;
        const uint32_t sB = sA + 32768;
        #pragma unroll
        for (int kc = 0; kc < 8; kc++) {
            uint32_t a4[4];
            const int rr = w * 16 + (mi & 1) * 8 + (l & 7);
            const int cba = kc * 2 + (mi >> 1);
            LDMATRIX_X4(a4[0], a4[1], a4[2], a4[3],
                        sA + rr * 256 + ((cba ^ (rr & 7)) << 4));
            #pragma unroll
            for (int jn = 0; jn < 16; jn += 2) {
                const int nr = (jn + (mi >> 1)) * 8 + (l & 7);
                const int cbb = kc * 2 + (mi & 1);
                uint32_t b0, b1, b2, b3;
                LDMATRIX_X4(b0, b1, b2, b3, sB + nr * 256 + ((cbb ^ (nr & 7)) << 4));
                MMA_16816(cacc[jn],     a4, b0, b1);
                MMA_16816(cacc[jn + 1], a4, b2, b3);
            }
        }
    }

    const int tr0 = t0 + w * 16 + (l >> 2);
    const int tr1 = tr0 + 8;
    float* dst = part + (size_t)sp * (B_ * T_ * KD_);
    #pragma unroll
    for (int jn = 0; jn < 16; jn++) {
        const int c = 8 * jn + 2 * (l & 3);
        *(float2*)(dst + ((size_t)b * T_ + tr0) * KD_ + c) = make_float2(cacc[jn][0], cacc[jn][1]);
        *(float2*)(dst + ((size_t)b * T_ + tr1) * KD_ + c) = make_float2(cacc[jn][2], cacc[jn][3]);
    }
}

__global__ void proj_reduce_kernel(const float4* __restrict__ part,
                                   const float* __restrict__ bu,
                                   float4* __restrict__ out)
{
    const int i = blockIdx.x * 256 + threadIdx.x;   // over B*T*KD/4
    const int c = (i & 31) * 4;
    const int S4 = (B_ * T_ * KD_) / 4;
    float4 a = part[i];
    float4 b = part[i + S4];
    float4 cc = part[i + 2 * S4];
    float4 d = part[i + 3 * S4];
    float4 bb = *(const float4*)(bu + c);
    float4 o;
    o.x = silu_f(a.x + b.x + cc.x + d.x + bb.x);
    o.y = silu_f(a.y + b.y + cc.y + d.y + bb.y);
    o.z = silu_f(a.z + b.z + cc.z + d.z + bb.z);
    o.w = silu_f(a.w + b.w + cc.w + d.w + bb.w);
    out[i] = o;
}

// ===========================================================================
// Flash attention via mma.sync (R11 proven config + Q via cp.async).
// BM=128, 8 warps x 16 rows. K/V loaded in PAIRS of 64-row s-tiles,
// double-buffered. Q/K carry sqrt(log2e) -> log2-domain S; exp via ex2.f16x2.
// Smem: Q 32KB | buf0 [K32|V32] | buf1 [K32|V32] = 160KB.
// ===========================================================================
#define BM 128
#define BN 64
#define ATTN_SMEM (32768 + 2 * 65536)

__global__ void __launch_bounds__(256, 1)
attn_mma_kernel(const __half* __restrict__ Qb, const __half* __restrict__ Kb,
                const __half* __restrict__ Vb, __half* __restrict__ Ph)
{
    extern __shared__ char smc[];
    const uint32_t sQ = smem_to_u32(smc);

    const int tid = threadIdx.x, w = tid >> 5, l = tid & 31;
    const int bid = blockIdx.x;
    const int bi  = 15 - (bid >> 5);       // q-tile index, heavy (15) first
    const int m   = bid & 31;
    const int q0  = bi * BM;
    const size_t mbase = (size_t)m * T_ * KD_;
    const int npairs = bi + 1;             // pairs of 64-row s-tiles

    // ---- group 0: Q tile [128 x 128] via cp.async
    {
        const __half* qs = Qb + mbase + (size_t)q0 * KD_;
        #pragma unroll
        for (int it = 0; it < 8; it++) {
            int idx = it * 256 + tid;
            int r = idx >> 4, cb = idx & 15;
            CP_ASYNC16(sQ + r * 256 + ((cb ^ (r & 7)) << 4),
                       qs + (size_t)r * KD_ + cb * 8);
        }
        CP_COMMIT();
    }
    // ---- group 1: K/V pair 0 into buf 0
    {
        const __half* ks = Kb + mbase;
        const __half* vs = Vb + mbase;
        #pragma unroll
        for (int it = 0; it < 8; it++) {
            int idx = it * 256 + tid;
            int r = idx >> 4, cb = idx & 15;
            int off = r * 256 + ((cb ^ (r & 7)) << 4);
            CP_ASYNC16(sQ + 32768 + off,         ks + (size_t)r * KD_ + cb * 8);
            CP_ASYNC16(sQ + 32768 + 32768 + off, vs + (size_t)r * KD_ + cb * 8);
        }
        CP_COMMIT();
    }
    cp_wait<1>();      // Q resident (pair 0 may still fly)
    __syncthreads();

    // ---- extract Q A-frags
    uint32_t qa[8][4];
    {
        const int mi = l >> 3;
        const int rr = w * 16 + (mi & 1) * 8 + (l & 7);
        #pragma unroll
        for (int kc = 0; kc < 8; kc++) {
            const int cb = kc * 2 + (mi >> 1);
            LDMATRIX_X4(qa[kc][0], qa[kc][1], qa[kc][2], qa[kc][3],
                        sQ + rr * 256 + ((cb ^ (rr & 7)) << 4));
        }
    }

    float oacc[16][4] = {};
    float lsum0 = 0.0f, lsum1 = 0.0f;
    const int r0g = q0 + w * 16 + (l >> 2);
    const int r1g = r0g + 8;

    #pragma unroll 1
    for (int p = 0; p < npairs; p++) {
        __syncthreads();   // prior compute done (protects buf (p+1)&1)
        if (p + 1 < npairs) {
            const int s1 = (p + 1) * 128;
            const uint32_t base = sQ + 32768 + ((p + 1) & 1) * 65536;
            const __half* ks = Kb + mbase + (size_t)s1 * KD_;
            const __half* vs = Vb + mbase + (size_t)s1 * KD_;
            #pragma unroll
            for (int it = 0; it < 8; it++) {
                int idx = it * 256 + tid;
                int r = idx >> 4, cb = idx & 15;
                int off = r * 256 + ((cb ^ (r & 7)) << 4);
                CP_ASYNC16(base + off,         ks + (size_t)r * KD_ + cb * 8);
                CP_ASYNC16(base + 32768 + off, vs + (size_t)r * KD_ + cb * 8);
            }
            CP_COMMIT();
            cp_wait<1>();
        } else {
            cp_wait<0>();
        }
        __syncthreads();

        const uint32_t bufK = sQ + 32768 + (p & 1) * 65536;
        const uint32_t bufV = bufK + 32768;

        #pragma unroll
        for (int sub = 0; sub < 2; sub++) {
            const int s0 = p * 128 + sub * BN;
            const uint32_t sK = bufK + sub * 64 * 256;
            const uint32_t sV = bufV + sub * 64 * 256;

            // ---- S = Q K^T  (log2-domain logits)
            float sacc[8][4] = {};
            {
                const int mi = l >> 3;
                #pragma unroll
                for (int kc = 0; kc < 8; kc++) {
                    #pragma unroll
                    for (int j = 0; j < 8; j += 2) {
                        const int nr = (j + (mi >> 1)) * 8 + (l & 7);
                        const int cb = kc * 2 + (mi & 1);
                        uint32_t b0, b1, b2, b3;
                        LDMATRIX_X4(b0, b1, b2, b3, sK + nr * 256 + ((cb ^ (nr & 7)) << 4));
                        MMA_16816(sacc[j],     qa[kc], b0, b1);
                        MMA_16816(sacc[j + 1], qa[kc], b2, b3);
                    }
                }
            }

            // ---- mask + ex2.f16x2 -> P A-frags (one MUFU per 2 values)
            uint32_t pa[4][4];
            {
                const int cb0 = s0 + 2 * (l & 3);
                #pragma unroll
                for (int j = 0; j < 8; j++) {
                    const int c0 = cb0 + 8 * j, c1 = c0 + 1;
                    float m00 = (c0 <= r0g) ? sacc[j][0] : -60.0f;
                    float m01 = (c1 <= r0g) ? sacc[j][1] : -60.0f;
                    float m10 = (c0 <= r1g) ? sacc[j][2] : -60.0f;
                    float m11 = (c1 <= r1g) ? sacc[j][3] : -60.0f;
                    __half2 ha = __floats2half2_rn(m00, m01);
                    __half2 hb = __floats2half2_rn(m10, m11);
                    uint32_t ua, ub;
                    asm("ex2.approx.f16x2 %0, %1;" : "=r"(ua) : "r"(*(uint32_t*)&ha));
                    asm("ex2.approx.f16x2 %0, %1;" : "=r"(ub) : "r"(*(uint32_t*)&hb));
                    float2 fa = __half22float2(*(__half2*)&ua);
                    float2 fb = __half22float2(*(__half2*)&ub);
                    lsum0 += fa.x + fa.y;
                    lsum1 += fb.x + fb.y;
                    const int kc2 = j >> 1, hi = (j & 1) * 2;
                    pa[kc2][hi + 0] = ua;
                    pa[kc2][hi + 1] = ub;
                }
            }

            // ---- O += P V
            {
                const int mi = l >> 3;
                #pragma unroll
                for (int kc2 = 0; kc2 < 4; kc2++) {
                    #pragma unroll
                    for (int j = 0; j < 16; j += 2) {
                        const int sr = kc2 * 16 + (mi & 1) * 8 + (l & 7);
                        const int cb = j + (mi >> 1);
                        uint32_t b0, b1, b2, b3;
                        LDMATRIX_X4_T(b0, b1, b2, b3, sV + sr * 256 + ((cb ^ (sr & 7)) << 4));
                        MMA_16816(oacc[j],     pa[kc2], b0, b1);
                        MMA_16816(oacc[j + 1], pa[kc2], b2, b3);
                    }
                }
            }
        }
    }

    // ---- epilogue
    lsum0 += __shfl_xor_sync(0xffffffffu, lsum0, 1);
    lsum0 += __shfl_xor_sync(0xffffffffu, lsum0, 2);
    lsum1 += __shfl_xor_sync(0xffffffffu, lsum1, 1);
    lsum1 += __shfl_xor_sync(0xffffffffu, lsum1, 2);
    const float li0 = 1.0f / lsum0, li1 = 1.0f / lsum1;

    const int b = m >> 3, h = m & 7;
    __half* base0 = Ph + ((size_t)b * T_ + r0g) * C_ + h * KD_ + 2 * (l & 3);
    __half* base1 = Ph + ((size_t)b * T_ + r1g) * C_ + h * KD_ + 2 * (l & 3);
    #pragma unroll
    for (int j = 0; j < 16; j++) {
        *(__half2*)(base0 + 8 * j) = __floats2half2_rn(oacc[j][0] * li0, oacc[j][1] * li0);
        *(__half2*)(base1 + 8 * j) = __floats2half2_rn(oacc[j][2] * li1, oacc[j][3] * li1);
    }
}

// ===========================================================================
extern "C" void kernel_launch(void* const* d_in, const int* in_sizes, int n_in,
                              void* d_out, int out_size)
{
    const float* x  = (const float*)d_in[0];
    const float* Wq = (const float*)d_in[1];
    const float* bq = (const float*)d_in[2];
    const float* Wk = (const float*)d_in[3];
    const float* bk = (const float*)d_in[4];
    const float* Wv = (const float*)d_in[5];
    const float* Wu = (const float*)d_in[6];
    const float* bu = (const float*)d_in[7];
    float* out = (float*)d_out;

    __half *xh, *wq5, *wk5, *wv, *wu, *qp, *kp, *vp, *ph;
    float* pacc;
    cudaGetSymbolAddress((void**)&xh,   g_xh);
    cudaGetSymbolAddress((void**)&wq5,  g_Wq5);
    cudaGetSymbolAddress((void**)&wk5,  g_Wk5);
    cudaGetSymbolAddress((void**)&wv,   g_Wv);
    cudaGetSymbolAddress((void**)&wu,   g_Wu);
    cudaGetSymbolAddress((void**)&qp,   g_Qh);
    cudaGetSymbolAddress((void**)&kp,   g_Kh);
    cudaGetSymbolAddress((void**)&vp,   g_Vh);
    cudaGetSymbolAddress((void**)&ph,   g_Ph);
    cudaGetSymbolAddress((void**)&pacc, g_acc);

    cudaFuncSetAttribute(attn_mma_kernel, cudaFuncAttributeMaxDynamicSharedMemorySize, ATTN_SMEM);
    cudaFuncSetAttribute(qkvconv_kernel, cudaFuncAttributeMaxDynamicSharedMemorySize, QKV_SMEM);
    cudaFuncSetAttribute(proj_partial_kernel, cudaFuncAttributeMaxDynamicSharedMemorySize, PROJ_SMEM);

    // 1/128^0.25 * sqrt(log2(e))  -> S lands in log2 domain
    const float qk_scale = 0.3570958376f;

    // ---- fused prepack (x + weights, 1 launch)
    pack_all_kernel<<<N_PACK / 256, 256>>>(x, Wq, Wk, Wv, Wu, xh, wq5, wk5, wv, wu);

    // ---- merged Q/K/V conv (fp16 A via cp.async, permuted weights)
    dim3 gqkv(T_ / 128, 24, B_);
    qkvconv_kernel<<<gqkv, 128, QKV_SMEM>>>(xh, wq5, wk5, wv, bq, bk, qp, kp, vp, qk_scale);

    // ---- attention (1D grid, heavy q-tiles first; double-buffered K/V)
    attn_mma_kernel<<<512, 256, ATTN_SMEM>>>(qp, kp, vp, ph);

    // ---- output projection: split-K partials + vectorized reduce
    dim3 gp(T_ / 128, PSPLIT, B_);
    proj_partial_kernel<<<gp, 256, PROJ_SMEM>>>(ph, wu, pacc);
    proj_reduce_kernel<<<(B_ * T_ * KD_) / 1024, 256>>>((const float4*)pacc, bu, (float4*)out);
}